// round 14
// baseline (speedup 1.0000x reference)
#include <cuda_runtime.h>
#include <cuda_bf16.h>
#include <cuda_fp16.h>
#include <math.h>
#include <stdint.h>

// ---------------- problem constants ----------------
#define NL   12
#define NH   12
#define DM   768
#define DFF  3072
#define NV   100256
#define DH   64
#define NB   2
#define NT   1024
#define MROWS (NB*NT)          // 2048
#define KP1  (3*DM)            // 2304
#define KP2  (3*DFF)           // 9216
#define NCB  392               // logits col blocks = ceil(NV/256)
#define LM0  20.0f             // fixed log-sum-exp offset (|logits| << 20)

// ---------------- scratch (device globals; no allocs allowed) ----------------
__device__ float g_x[MROWS*DM];
__device__ float g_q[MROWS*DM];
__device__ float g_k[MROWS*DM];
__device__ float g_v[MROWS*DM];
__device__ float g_rowloss[MROWS];
__device__ float g_partial[(size_t)MROWS*NCB];
// triple-packed bf16 activations (A operands, body)
__device__ __nv_bfloat16 g_hp [MROWS*KP1];
__device__ __nv_bfloat16 g_atp[MROWS*KP1];
__device__ __nv_bfloat16 g_ffp[(size_t)MROWS*KP2];
// fp16 final-LN activations (logits A operand)
__device__ __half g_hf[MROWS*DM];
// triple-packed, transposed bf16 weights (body B operands, [N, 3K] K-major)
__device__ __nv_bfloat16 g_wqp[(size_t)NL*DM*KP1];
__device__ __nv_bfloat16 g_wkp[(size_t)NL*DM*KP1];
__device__ __nv_bfloat16 g_wvp[(size_t)NL*DM*KP1];
__device__ __nv_bfloat16 g_wop[(size_t)NL*DM*KP1];
__device__ __nv_bfloat16 g_w1p[(size_t)NL*DFF*KP1];
__device__ __nv_bfloat16 g_w2p[(size_t)NL*DM*KP2];
// fp16 transposed w_out [NV, DM]
__device__ __half g_wouth[(size_t)NV*DM];

// ---------------- PTX helpers ----------------
template<int DT>
__device__ __forceinline__ void mma_16816(float* d, const unsigned* a, const unsigned* b) {
    if constexpr (DT == 0) {
        asm volatile(
            "mma.sync.aligned.m16n8k16.row.col.f32.bf16.bf16.f32 "
            "{%0,%1,%2,%3}, {%4,%5,%6,%7}, {%8,%9}, {%0,%1,%2,%3};\n"
            : "+f"(d[0]), "+f"(d[1]), "+f"(d[2]), "+f"(d[3])
            : "r"(a[0]), "r"(a[1]), "r"(a[2]), "r"(a[3]), "r"(b[0]), "r"(b[1]));
    } else {
        asm volatile(
            "mma.sync.aligned.m16n8k16.row.col.f32.f16.f16.f32 "
            "{%0,%1,%2,%3}, {%4,%5,%6,%7}, {%8,%9}, {%0,%1,%2,%3};\n"
            : "+f"(d[0]), "+f"(d[1]), "+f"(d[2]), "+f"(d[3])
            : "r"(a[0]), "r"(a[1]), "r"(a[2]), "r"(a[3]), "r"(b[0]), "r"(b[1]));
    }
}
__device__ __forceinline__ void ldsm4(unsigned addr, unsigned& r0, unsigned& r1,
                                      unsigned& r2, unsigned& r3) {
    asm volatile("ldmatrix.sync.aligned.m8n8.x4.shared.b16 {%0,%1,%2,%3}, [%4];"
                 : "=r"(r0), "=r"(r1), "=r"(r2), "=r"(r3) : "r"(addr));
}
__device__ __forceinline__ void cpasync16(unsigned dst, const void* src, int srcbytes) {
    asm volatile("cp.async.cg.shared.global [%0], [%1], 16, %2;"
                 :: "r"(dst), "l"(src), "r"(srcbytes));
}
__device__ __forceinline__ void cp_commit() {
    asm volatile("cp.async.commit_group;" ::: "memory");
}
__device__ __forceinline__ void cp_wait0() {
    asm volatile("cp.async.wait_group 0;" ::: "memory");
}
__device__ __forceinline__ void cp_wait1() {
    asm volatile("cp.async.wait_group 1;" ::: "memory");
}
// A triple (hi, lo, hi); pairs with B triple (hi, hi, lo)
__device__ __forceinline__ unsigned short bf16bits(float v) {
    __nv_bfloat16 h = __float2bfloat16(v);
    return reinterpret_cast<unsigned short&>(h);
}
__device__ __forceinline__ void store_triple2(__nv_bfloat16* p, float v0, float v1) {
    unsigned short h0 = bf16bits(v0);
    float f0; { __nv_bfloat16 t = reinterpret_cast<__nv_bfloat16&>(h0); f0 = __bfloat162float(t); }
    unsigned short l0 = bf16bits(v0 - f0);
    unsigned short h1 = bf16bits(v1);
    float f1; { __nv_bfloat16 t = reinterpret_cast<__nv_bfloat16&>(h1); f1 = __bfloat162float(t); }
    unsigned short l1 = bf16bits(v1 - f1);
    unsigned* q = reinterpret_cast<unsigned*>(p);
    q[0] = (unsigned)h0 | ((unsigned)l0 << 16);
    q[1] = (unsigned)h0 | ((unsigned)h1 << 16);
    q[2] = (unsigned)l1 | ((unsigned)h1 << 16);
}

// ---------------- merged weight pack: all 6 body weights ---------------------
__global__ void pack_all_kernel(const float* __restrict__ wq, const float* __restrict__ wk,
                                const float* __restrict__ wv, const float* __restrict__ wo,
                                const float* __restrict__ w1, const float* __restrict__ w2,
                                __nv_bfloat16* __restrict__ wqp, __nv_bfloat16* __restrict__ wkp,
                                __nv_bfloat16* __restrict__ wvp, __nv_bfloat16* __restrict__ wop,
                                __nv_bfloat16* __restrict__ w1p, __nv_bfloat16* __restrict__ w2p)
{
    __shared__ float sm[32][33];
    int bid = blockIdx.x;
    const float* W; __nv_bfloat16* Wp;
    int K, N, bx, by, layer;
    if (bid < 27648) {
        int wid = bid / 6912, rem = bid % 6912;
        layer = rem / 576; int rr = rem % 576;
        bx = rr % 24; by = rr / 24; K = DM; N = DM;
        W  = (wid == 0) ? wq  : (wid == 1) ? wk  : (wid == 2) ? wv  : wo;
        Wp = (wid == 0) ? wqp : (wid == 1) ? wkp : (wid == 2) ? wvp : wop;
    } else if (bid < 55296) {
        int rem = bid - 27648;
        layer = rem / 2304; int rr = rem % 2304;
        bx = rr % 96; by = rr / 96; K = DM; N = DFF;
        W = w1; Wp = w1p;
    } else {
        int rem = bid - 55296;
        layer = rem / 2304; int rr = rem % 2304;
        bx = rr % 24; by = rr / 24; K = DFF; N = DM;
        W = w2; Wp = w2p;
    }
    const size_t lw = (size_t)layer * K * N;
    const size_t lo = (size_t)layer * N * 3 * K;
    int n0 = bx * 32, k0 = by * 32;
    int tx = threadIdx.x, ty = threadIdx.y;   // 32 x 8
#pragma unroll
    for (int j = 0; j < 4; j++) {
        int kk = ty + j * 8;
        sm[kk][tx] = W[lw + (size_t)(k0 + kk) * N + n0 + tx];
    }
    __syncthreads();
#pragma unroll
    for (int j = 0; j < 4; j++) {
        int nl = ty + j * 8;
        float v = sm[tx][nl];
        __nv_bfloat16 hi  = __float2bfloat16(v);
        __nv_bfloat16 lo2 = __float2bfloat16(v - __bfloat162float(hi));
        size_t o = lo + (size_t)(n0 + nl) * (3 * K) + 3 * (k0 + tx);
        Wp[o] = hi; Wp[o + 1] = hi; Wp[o + 2] = lo2;
    }
}

// ---------------- w_out transpose: W[K,N] fp32 -> W'[N,K] fp16 ---------------
__global__ void packw_fp16_kernel(const float* __restrict__ W,
                                  __half* __restrict__ Wp, int K, int N)
{
    __shared__ float sm[32][33];
    int n0 = blockIdx.x * 32, k0 = blockIdx.y * 32;
    int tx = threadIdx.x, ty = threadIdx.y;
#pragma unroll
    for (int j = 0; j < 4; j++) {
        int kk = ty + j * 8;
        sm[kk][tx] = W[(size_t)(k0 + kk) * N + n0 + tx];
    }
    __syncthreads();
#pragma unroll
    for (int j = 0; j < 4; j++) {
        int nl = ty + j * 8;
        Wp[(size_t)(n0 + nl) * K + k0 + tx] = __float2half_rn(sm[tx][nl]);
    }
}

// ---------------- embedding + sinusoidal positional encoding ----------------
__global__ void embed_kernel(const int* __restrict__ idx,
                             const float* __restrict__ emb,
                             float* __restrict__ x)
{
    int i = blockIdx.x * blockDim.x + threadIdx.x;
    if (i >= MROWS * DM) return;
    int d  = i % DM;
    int bt = i / DM;
    int t  = bt % NT;
    int tok = idx[bt];
    int ii = d & ~1;
    float div = expf(-(float)ii * (logf(10000.0f) / (float)DM));
    float ang = (float)t * div;
    float pe  = (d & 1) ? cosf(ang) : sinf(ang);
    x[i] = emb[(size_t)tok * DM + d] + pe;
}

// ---------------- warp-per-row layernorm -> triple-packed bf16 ---------------
__global__ void __launch_bounds__(256)
ln_kernel(const float* __restrict__ x,
          const float* __restrict__ s,
          const float* __restrict__ b,
          __nv_bfloat16* __restrict__ yp)
{
    int w = threadIdx.x >> 5, lane = threadIdx.x & 31;
    int row = blockIdx.x * 8 + w;
    const float* xr = x + (size_t)row * DM;
    float4 xs[6];
    float s1 = 0.0f, s2 = 0.0f;
#pragma unroll
    for (int j = 0; j < 6; j++) {
        xs[j] = *(const float4*)&xr[(lane + j * 32) * 4];
        s1 += xs[j].x + xs[j].y + xs[j].z + xs[j].w;
        s2 += xs[j].x * xs[j].x + xs[j].y * xs[j].y
            + xs[j].z * xs[j].z + xs[j].w * xs[j].w;
    }
#pragma unroll
    for (int off = 16; off > 0; off >>= 1) {
        s1 += __shfl_xor_sync(0xffffffff, s1, off);
        s2 += __shfl_xor_sync(0xffffffff, s2, off);
    }
    float mu  = s1 * (1.0f / DM);
    float var = s2 * (1.0f / DM) - mu * mu;
    float r = rsqrtf(var + 1e-5f);

    __nv_bfloat16* yr = yp + (size_t)row * KP1;
#pragma unroll
    for (int j = 0; j < 6; j++) {
        int c = (lane + j * 32) * 4;
        float y0 = (xs[j].x - mu) * r * s[c    ] + b[c    ];
        float y1 = (xs[j].y - mu) * r * s[c + 1] + b[c + 1];
        float y2 = (xs[j].z - mu) * r * s[c + 2] + b[c + 2];
        float y3 = (xs[j].w - mu) * r * s[c + 3] + b[c + 3];
        store_triple2(yr + 3 * c,       y0, y1);
        store_triple2(yr + 3 * (c + 2), y2, y3);
    }
}

// ---------------- warp-per-row final layernorm -> fp16 -----------------------
__global__ void __launch_bounds__(256)
ln_fp16_kernel(const float* __restrict__ x,
               const float* __restrict__ s,
               const float* __restrict__ b,
               __half* __restrict__ yh)
{
    int w = threadIdx.x >> 5, lane = threadIdx.x & 31;
    int row = blockIdx.x * 8 + w;
    const float* xr = x + (size_t)row * DM;
    float4 xs[6];
    float s1 = 0.0f, s2 = 0.0f;
#pragma unroll
    for (int j = 0; j < 6; j++) {
        xs[j] = *(const float4*)&xr[(lane + j * 32) * 4];
        s1 += xs[j].x + xs[j].y + xs[j].z + xs[j].w;
        s2 += xs[j].x * xs[j].x + xs[j].y * xs[j].y
            + xs[j].z * xs[j].z + xs[j].w * xs[j].w;
    }
#pragma unroll
    for (int off = 16; off > 0; off >>= 1) {
        s1 += __shfl_xor_sync(0xffffffff, s1, off);
        s2 += __shfl_xor_sync(0xffffffff, s2, off);
    }
    float mu  = s1 * (1.0f / DM);
    float var = s2 * (1.0f / DM) - mu * mu;
    float r = rsqrtf(var + 1e-5f);

    __half* yr = yh + (size_t)row * DM;
#pragma unroll
    for (int j = 0; j < 6; j++) {
        int c = (lane + j * 32) * 4;
        float y0 = (xs[j].x - mu) * r * s[c    ] + b[c    ];
        float y1 = (xs[j].y - mu) * r * s[c + 1] + b[c + 1];
        float y2 = (xs[j].z - mu) * r * s[c + 2] + b[c + 2];
        float y3 = (xs[j].w - mu) * r * s[c + 3] + b[c + 3];
        *reinterpret_cast<__half2*>(yr + c) =
            __halves2half2(__float2half_rn(y0), __float2half_rn(y1));
        *reinterpret_cast<__half2*>(yr + c + 2) =
            __halves2half2(__float2half_rn(y2), __float2half_rn(y3));
    }
}

// ---------------- 16-bit mma.sync GEMM (bf16 or fp16) ------------------------
// EPI: 0 = +bias ; 1 = relu(+bias)->triple-pack ; 2 = +bias+R ;
//      4 = +bias, write C, AND per-row sum of exp(x-LM0) -> epart
struct GemmArgs3 {
    const __nv_bfloat16* B[3];
    float*               C[3];
    const float*         bias[3];
};

template<int BM, int BN, int MT, int NTT, int EPI, int DT>
__global__ void __launch_bounds__(256, 1)
mma_gemm(const __nv_bfloat16* __restrict__ A, GemmArgs3 ga,
         const float* __restrict__ R, __nv_bfloat16* __restrict__ P3,
         float* __restrict__ epart, int Ncols, int Kp)
{
    constexpr int BK = 64, ST = 72;
    constexpr int ROWS = BM + BN;
    constexpr int NCH  = ROWS * 8 / 256;
    extern __shared__ __align__(128) __nv_bfloat16 smem[];
    __shared__ float sm_es[4][BM];

    const int z = blockIdx.z;
    const __nv_bfloat16* __restrict__ Bg   = ga.B[z];
    float*               __restrict__ C    = ga.C[z];
    const float*         __restrict__ bias = ga.bias[z];

    const int tid  = threadIdx.x;
    const int lane = tid & 31;
    const int w    = tid >> 5;
    const int wr   = w >> 2;
    const int wc   = w & 3;
    const int row0 = blockIdx.x * BM;
    const int col0 = blockIdx.y * BN;
    const int mB   = wr * MT * 16;
    const int nB   = wc * NTT * 8;
    const unsigned sbase = (unsigned)__cvta_generic_to_shared(smem);

    float acc[MT][NTT][4];
#pragma unroll
    for (int i = 0; i < MT; i++)
#pragma unroll
        for (int j = 0; j < NTT; j++)
#pragma unroll
            for (int q = 0; q < 4; q++) acc[i][j][q] = 0.0f;

    auto load_stage = [&](int s, int k0) {
        unsigned dbase = sbase + (unsigned)(s * ROWS * ST) * 2;
#pragma unroll
        for (int i = 0; i < NCH; i++) {
            int ch  = tid + i * 256;
            int row = ch >> 3;
            int kq  = (ch & 7) * 8;
            const __nv_bfloat16* src;
            int bytes = 16;
            if (row < BM) {
                src = A + (size_t)(row0 + row) * Kp + k0 + kq;
            } else {
                int gn = col0 + row - BM;
                if (gn >= Ncols) { gn = Ncols - 1; bytes = 0; }
                src = Bg + (size_t)gn * Kp + k0 + kq;
            }
            cpasync16(dbase + (unsigned)(row * ST + kq) * 2, src, bytes);
        }
    };

    const int lrow  = lane & 15;
    const int lcolb = (lane >> 4) * 8;
    const int lrow8 = lane & 7;

    auto compute_stage = [&](int s) {
        unsigned base = sbase + (unsigned)(s * ROWS * ST) * 2;
#pragma unroll
        for (int ks = 0; ks < 4; ks++) {
            unsigned a[MT][4];
#pragma unroll
            for (int mt = 0; mt < MT; mt++) {
                unsigned off = (unsigned)((mB + mt * 16 + lrow) * ST + ks * 16 + lcolb) * 2;
                ldsm4(base + off, a[mt][0], a[mt][1], a[mt][2], a[mt][3]);
            }
            unsigned b[NTT][2];
            if constexpr (NTT == 3) {
                unsigned r0, r1, r2, r3;
                unsigned off0 = (unsigned)((BM + nB + lrow) * ST + ks * 16 + lcolb) * 2;
                ldsm4(base + off0, r0, r1, r2, r3);
                b[0][0] = r0; b[0][1] = r2;
                b[1][0] = r1; b[1][1] = r3;
                unsigned off1 = (unsigned)((BM + nB + 16 + lrow8) * ST + ks * 16 + lcolb) * 2;
                ldsm4(base + off1, r0, r1, r2, r3);
                b[2][0] = r0; b[2][1] = r2;
            } else {
#pragma unroll
                for (int np = 0; np < NTT / 2; np++) {
                    unsigned r0, r1, r2, r3;
                    unsigned off = (unsigned)((BM + nB + np * 16 + lrow) * ST + ks * 16 + lcolb) * 2;
                    ldsm4(base + off, r0, r1, r2, r3);
                    b[np * 2][0] = r0;     b[np * 2][1] = r2;
                    b[np * 2 + 1][0] = r1; b[np * 2 + 1][1] = r3;
                }
            }
#pragma unroll
            for (int mt = 0; mt < MT; mt++)
#pragma unroll
                for (int nt = 0; nt < NTT; nt++)
                    mma_16816<DT>(acc[mt][nt], a[mt], b[nt]);
        }
    };

    const int NIT = Kp / BK;
    load_stage(0, 0);  cp_commit();
    load_stage(1, BK); cp_commit();

#pragma unroll 1
    for (int it = 0; it < NIT; ++it) {
        if (it + 1 < NIT) cp_wait1(); else cp_wait0();
        __syncthreads();
        compute_stage(it % 3);
        if (it + 2 < NIT) { load_stage((it + 2) % 3, (it + 2) * BK); cp_commit(); }
    }

    // ---------------- epilogue ----------------
    const int grp = lane >> 2;
    const int tig = lane & 3;
#pragma unroll
    for (int mt = 0; mt < MT; mt++) {
        int r = row0 + mB + mt * 16 + grp;
        float e0 = 0.0f, e1 = 0.0f;
#pragma unroll
        for (int nt = 0; nt < NTT; nt++) {
            int c = col0 + nB + nt * 8 + tig * 2;
            if (c < Ncols) {
                float x0 = acc[mt][nt][0], x1 = acc[mt][nt][1];
                float x2 = acc[mt][nt][2], x3 = acc[mt][nt][3];
                if (bias) {
                    float b0 = bias[c], b1 = bias[c + 1];
                    x0 += b0; x1 += b1; x2 += b0; x3 += b1;
                }
                if (EPI == 1) {
                    x0 = fmaxf(x0, 0.f); x1 = fmaxf(x1, 0.f);
                    x2 = fmaxf(x2, 0.f); x3 = fmaxf(x3, 0.f);
                    size_t kp3 = 3 * (size_t)Ncols;
                    store_triple2(P3 + (size_t)r       * kp3 + 3 * c, x0, x1);
                    store_triple2(P3 + (size_t)(r + 8) * kp3 + 3 * c, x2, x3);
                } else {
                    if (EPI == 2) {
                        const float2 ra = *(const float2*)&R[(size_t)r       * Ncols + c];
                        const float2 rb = *(const float2*)&R[(size_t)(r + 8) * Ncols + c];
                        x0 += ra.x; x1 += ra.y; x2 += rb.x; x3 += rb.y;
                    }
                    if (EPI == 4) {
                        e0 += __expf(x0 - LM0) + __expf(x1 - LM0);
                        e1 += __expf(x2 - LM0) + __expf(x3 - LM0);
                    }
                    *(float2*)&C[(size_t)r       * Ncols + c] = make_float2(x0, x1);
                    *(float2*)&C[(size_t)(r + 8) * Ncols + c] = make_float2(x2, x3);
                }
            }
        }
        if constexpr (EPI == 4) {
            e0 += __shfl_xor_sync(0xffffffff, e0, 1);
            e0 += __shfl_xor_sync(0xffffffff, e0, 2);
            e1 += __shfl_xor_sync(0xffffffff, e1, 1);
            e1 += __shfl_xor_sync(0xffffffff, e1, 2);
            if (tig == 0) {
                sm_es[wc][mB + mt * 16 + grp]     = e0;
                sm_es[wc][mB + mt * 16 + grp + 8] = e1;
            }
        }
    }
    if constexpr (EPI == 4) {
        __syncthreads();
        if (tid < BM) {
            float es = sm_es[0][tid] + sm_es[1][tid] + sm_es[2][tid] + sm_es[3][tid];
            epart[(size_t)(row0 + tid) * gridDim.y + blockIdx.y] = es;
        }
    }
}

// ---------------- pair-split key-parallel causal attention -------------------
// 512 threads (16 warps), warp = one query row. Lane PAIR shares one key:
// each lane holds half of q (qh[32]) -> fewer regs -> 2 CTAs/SM.
// After the pair-combine, both lanes of a pair hold identical p; the
// xor{2,4,8,16} butterfly therefore sums each of the 16 keys EXACTLY ONCE.
#define QR 16
__global__ void __launch_bounds__(512, 2)
attn_kernel(const float* __restrict__ q,
            const float* __restrict__ k,
            const float* __restrict__ v,
            __nv_bfloat16* __restrict__ op)
{
    __shared__ __align__(16) float kt[64 * 65 + 16];  // [d][key], +16 for d>=32
    __shared__ __align__(16) float vs[64 * 64];       // [key][d]

    const int tid  = threadIdx.x;
    const int wid  = tid >> 5;
    const int lane = tid & 31;
    const int half = lane & 1;
    const int key16 = lane >> 1;          // 0..15
    const int qt0  = blockIdx.x * QR;
    const int h    = blockIdx.y;
    const int b    = blockIdx.z;
    const int t    = qt0 + wid;

    // each lane holds one half of q
    float qh[32];
    size_t qb = ((size_t)(b * NT + t) * NH + h) * DH + half * 32;
#pragma unroll
    for (int j = 0; j < 32; j += 4) {
        float4 qv = *(const float4*)&q[qb + j];
        qh[j] = qv.x; qh[j + 1] = qv.y; qh[j + 2] = qv.z; qh[j + 3] = qv.w;
    }
    const int kb = half * (32 * 65 + 16);

    float m = -INFINITY, l = 0.0f, o0 = 0.0f, o1 = 0.0f;
    const float scale = 0.125f;
    const int lr = tid >> 3;              // 0..63 key row
    const int lc = (tid & 7) * 8;         // 0..56 d chunk
    const int koff = (lc >= 32) ? 16 : 0;

    for (int s0 = 0; s0 <= qt0 + QR - 1; s0 += 64) {
        __syncthreads();
        {
            size_t gb = ((size_t)(b * NT + s0 + lr) * NH + h) * DH + lc;
            float4 k0 = *(const float4*)&k[gb];
            float4 k1 = *(const float4*)&k[gb + 4];
            kt[(lc + 0) * 65 + koff + lr] = k0.x; kt[(lc + 1) * 65 + koff + lr] = k0.y;
            kt[(lc + 2) * 65 + koff + lr] = k0.z; kt[(lc + 3) * 65 + koff + lr] = k0.w;
            kt[(lc + 4) * 65 + koff + lr] = k1.x; kt[(lc + 5) * 65 + koff + lr] = k1.y;
            kt[(lc + 6) * 65 + koff + lr] = k1.z; kt[(lc + 7) * 65 + koff + lr] = k1.w;
            *(float4*)&vs[lr * 64 + lc]     = *(const float4*)&v[gb];
            *(float4*)&vs[lr * 64 + lc + 4] = *(const float4*)&v[gb + 4];
        }
        __syncthreads();

        int nvalid = t - s0 + 1;
        if (nvalid > 64) nvalid = 64;
#pragma unroll 1
        for (int sb = 0; sb < nvalid; sb += 16) {
            int key = sb + key16;
            float a = 0.0f;
#pragma unroll
            for (int j = 0; j < 32; j++)
                a = fmaf(qh[j], kt[kb + j * 65 + key], a);
            a += __shfl_xor_sync(0xffffffff, a, 1);   // pair halves combine
            float sc = (key < nvalid) ? a * scale : -INFINITY;

            float mb = sc;                            // pairs equal: skip xor 1
            mb = fmaxf(mb, __shfl_xor_sync(0xffffffff, mb, 2));
            mb = fmaxf(mb, __shfl_xor_sync(0xffffffff, mb, 4));
            mb = fmaxf(mb, __shfl_xor_sync(0xffffffff, mb, 8));
            mb = fmaxf(mb, __shfl_xor_sync(0xffffffff, mb, 16));
            float mn = fmaxf(m, mb);
            float c  = __expf(m - mn);
            float p  = __expf(sc - mn);
            float ps = p;
            ps += __shfl_xor_sync(0xffffffff, ps, 2);
            ps += __shfl_xor_sync(0xffffffff, ps, 4);
            ps += __shfl_xor_sync(0xffffffff, ps, 8);
            ps += __shfl_xor_sync(0xffffffff, ps, 16);
            o0 *= c; o1 *= c;
            l = l * c + ps;        // ps covers each key ONCE (same-parity lanes)
            m = mn;
#pragma unroll
            for (int i = 0; i < 16; i++) {
                float pi = __shfl_sync(0xffffffff, p, 2 * i);
                float2 vv = *(const float2*)&vs[(sb + i) * 64 + 2 * lane];
                o0 = fmaf(pi, vv.x, o0);
                o1 = fmaf(pi, vv.y, o1);
            }
        }
    }
    float inv = 1.0f / l;
    size_t tb = (size_t)(b * NT + t) * KP1 + 3 * (h * DH + 2 * lane);
    store_triple2(op + tb, o0 * inv, o1 * inv);
}

// ---------------- loss: gather partial exp-sums + target logit --------------
__global__ void loss_final_kernel(const float* __restrict__ partial,
                                  const float* __restrict__ logits,
                                  const int* __restrict__ tgt,
                                  float* __restrict__ rowloss)
{
    int r    = blockIdx.x * 8 + (threadIdx.x >> 5);
    int lane = threadIdx.x & 31;
    const float* pr = partial + (size_t)r * NCB;
    float s = 0.0f;
    for (int j = lane; j < NCB; j += 32) s += pr[j];
#pragma unroll
    for (int off = 16; off > 0; off >>= 1)
        s += __shfl_xor_sync(0xffffffff, s, off);
    if (lane == 0)
        rowloss[r] = LM0 + logf(s) - logits[(size_t)r * NV + tgt[r]];
}

__global__ void loss_reduce_kernel(const float* __restrict__ rowloss,
                                   float* __restrict__ out)
{
    __shared__ float sh[256];
    int tid = threadIdx.x;
    float s = 0.0f;
    for (int i = tid; i < MROWS; i += 256) s += rowloss[i];
    sh[tid] = s; __syncthreads();
    for (int o = 128; o > 0; o >>= 1) {
        if (tid < o) sh[tid] += sh[tid + o];
        __syncthreads();
    }
    if (tid == 0) out[0] = sh[0] * (1.0f / MROWS);
}

// ---------------- host driver ----------------
extern "C" void kernel_launch(void* const* d_in, const int* in_sizes, int n_in,
                              void* d_out, int out_size)
{
    const int*   idx     = (const int*)  d_in[0];
    const int*   targets = (const int*)  d_in[1];
    const float* emb     = (const float*)d_in[2];
    const float* wq      = (const float*)d_in[3];
    const float* wk      = (const float*)d_in[4];
    const float* wv      = (const float*)d_in[5];
    const float* wo      = (const float*)d_in[6];
    const float* bo      = (const float*)d_in[7];
    const float* ln1_s   = (const float*)d_in[8];
    const float* ln1_b   = (const float*)d_in[9];
    const float* ln2_s   = (const float*)d_in[10];
    const float* ln2_b   = (const float*)d_in[11];
    const float* w1      = (const float*)d_in[12];
    const float* b1      = (const float*)d_in[13];
    const float* w2      = (const float*)d_in[14];
    const float* b2      = (const float*)d_in[15];
    const float* lnf_s   = (const float*)d_in[16];
    const float* lnf_b   = (const float*)d_in[17];
    const float* w_out   = (const float*)d_in[18];
    const float* b_out   = (const float*)d_in[19];
    float* out = (float*)d_out;

    float *x, *q, *k, *v, *rl, *pt;
    __nv_bfloat16 *hp, *atp, *ffp, *wqp, *wkp, *wvp, *wop, *w1p, *w2p;
    __half *hf, *wouth;
    cudaGetSymbolAddress((void**)&x,     g_x);
    cudaGetSymbolAddress((void**)&q,     g_q);
    cudaGetSymbolAddress((void**)&k,     g_k);
    cudaGetSymbolAddress((void**)&v,     g_v);
    cudaGetSymbolAddress((void**)&rl,    g_rowloss);
    cudaGetSymbolAddress((void**)&pt,    g_partial);
    cudaGetSymbolAddress((void**)&hp,    g_hp);
    cudaGetSymbolAddress((void**)&atp,   g_atp);
    cudaGetSymbolAddress((void**)&ffp,   g_ffp);
    cudaGetSymbolAddress((void**)&hf,    g_hf);
    cudaGetSymbolAddress((void**)&wqp,   g_wqp);
    cudaGetSymbolAddress((void**)&wkp,   g_wkp);
    cudaGetSymbolAddress((void**)&wvp,   g_wvp);
    cudaGetSymbolAddress((void**)&wop,   g_wop);
    cudaGetSymbolAddress((void**)&w1p,   g_w1p);
    cudaGetSymbolAddress((void**)&w2p,   g_w2p);
    cudaGetSymbolAddress((void**)&wouth, g_wouth);

    const int SM_128 = 3 * (128 + 128) * 72 * 2;   // 110592
    const int SM_96  = 3 * (128 +  96) * 72 * 2;   //  96768
    const int SM_256 = 3 * (128 + 256) * 72 * 2;   // 165888
    cudaFuncSetAttribute(mma_gemm<128,128,4,4,0,0>, cudaFuncAttributeMaxDynamicSharedMemorySize, SM_128);
    cudaFuncSetAttribute(mma_gemm<128,128,4,4,1,0>, cudaFuncAttributeMaxDynamicSharedMemorySize, SM_128);
    cudaFuncSetAttribute(mma_gemm<128,96,4,3,2,0>,  cudaFuncAttributeMaxDynamicSharedMemorySize, SM_96);
    cudaFuncSetAttribute(mma_gemm<128,256,4,8,4,1>, cudaFuncAttributeMaxDynamicSharedMemorySize, SM_256);

    pack_all_kernel<<<82944, dim3(32, 8)>>>(wq, wk, wv, wo, w1, w2,
                                            wqp, wkp, wvp, wop, w1p, w2p);
    packw_fp16_kernel<<<dim3(NV / 32, DM / 32, 1), dim3(32, 8)>>>(w_out, wouth, DM, NV);
    embed_kernel<<<(MROWS * DM + 255) / 256, 256>>>(idx, emb, x);

    for (int l = 0; l < NL; l++) {
        size_t oq = (size_t)l * DM * KP1;
        size_t o1 = (size_t)l * DFF * KP1;
        size_t o2 = (size_t)l * DM * KP2;

        ln_kernel<<<MROWS / 8, 256>>>(x, ln1_s + l * DM, ln1_b + l * DM, hp);

        {   // q,k,v = h @ w{q,k,v}
            GemmArgs3 ga = {};
            ga.B[0] = wqp + oq; ga.B[1] = wkp + oq; ga.B[2] = wvp + oq;
            ga.C[0] = q; ga.C[1] = k; ga.C[2] = v;
            mma_gemm<128,128,4,4,0,0><<<dim3(16, 6, 3), 256, SM_128>>>(
                hp, ga, nullptr, nullptr, nullptr, DM, KP1);
        }

        attn_kernel<<<dim3(NT / QR, NH, NB), 512>>>(q, k, v, atp);

        {   // x = x + att @ wo + bo
            GemmArgs3 ga = {};
            ga.B[0] = wop + oq; ga.C[0] = x; ga.bias[0] = bo + l * DM;
            mma_gemm<128,96,4,3,2,0><<<dim3(16, 8, 1), 256, SM_96>>>(
                atp, ga, x, nullptr, nullptr, DM, KP1);
        }

        ln_kernel<<<MROWS / 8, 256>>>(x, ln2_s + l * DM, ln2_b + l * DM, hp);

        {   // ff = relu(h @ w1 + b1)
            GemmArgs3 ga = {};
            ga.B[0] = w1p + o1; ga.bias[0] = b1 + l * DFF;
            mma_gemm<128,128,4,4,1,0><<<dim3(16, 24, 1), 256, SM_128>>>(
                hp, ga, nullptr, ffp, nullptr, DFF, KP1);
        }

        {   // x = x + ff @ w2 + b2
            GemmArgs3 ga = {};
            ga.B[0] = w2p + o2; ga.C[0] = x; ga.bias[0] = b2 + l * DM;
            mma_gemm<128,96,4,3,2,0><<<dim3(16, 8, 1), 256, SM_96>>>(
                ffp, ga, x, nullptr, nullptr, DM, KP2);
        }
    }

    // h = LNf(x) -> fp16
    ln_fp16_kernel<<<MROWS / 8, 256>>>(x, lnf_s, lnf_b, hf);

    // logits = h @ w_out + b_out, fused per-row exp-sum partials (EPI=4)
    {
        GemmArgs3 ga = {};
        ga.B[0] = (const __nv_bfloat16*)wouth;
        ga.C[0] = out; ga.bias[0] = b_out;
        mma_gemm<128,256,4,8,4,1><<<dim3(16, NCB, 1), 256, SM_256>>>(
            (const __nv_bfloat16*)hf, ga, nullptr, nullptr, pt, NV, DM);
    }

    // loss: gather partials + target logit, then mean
    loss_final_kernel<<<MROWS / 8, 256>>>(pt, out, targets, rl);
    loss_reduce_kernel<<<1, 256>>>(rl, out + (size_t)MROWS * NV);
}

// round 15
// speedup vs baseline: 1.0165x; 1.0165x over previous
#include <cuda_runtime.h>
#include <cuda_bf16.h>
#include <cuda_fp16.h>
#include <math.h>
#include <stdint.h>

// ---------------- problem constants ----------------
#define NL   12
#define NH   12
#define DM   768
#define DFF  3072
#define NV   100256
#define DH   64
#define NB   2
#define NT   1024
#define MROWS (NB*NT)          // 2048
#define KP1  (3*DM)            // 2304
#define KP2  (3*DFF)           // 9216
#define NCB  392               // logits col blocks = ceil(NV/256)
#define LM0  20.0f             // fixed log-sum-exp offset (|logits| << 20)

// ---------------- scratch (device globals; no allocs allowed) ----------------
__device__ float g_x[MROWS*DM];
__device__ float g_q[MROWS*DM];
__device__ float g_k[MROWS*DM];
__device__ float g_v[MROWS*DM];
__device__ float g_rowloss[MROWS];
__device__ float g_partial[(size_t)MROWS*NCB];
// triple-packed bf16 activations (A operands, body)
__device__ __nv_bfloat16 g_hp [MROWS*KP1];
__device__ __nv_bfloat16 g_atp[MROWS*KP1];
__device__ __nv_bfloat16 g_ffp[(size_t)MROWS*KP2];
// fp16 final-LN activations (logits A operand)
__device__ __half g_hf[MROWS*DM];
// triple-packed, transposed bf16 weights (body B operands, [N, 3K] K-major)
__device__ __nv_bfloat16 g_wqp[(size_t)NL*DM*KP1];
__device__ __nv_bfloat16 g_wkp[(size_t)NL*DM*KP1];
__device__ __nv_bfloat16 g_wvp[(size_t)NL*DM*KP1];
__device__ __nv_bfloat16 g_wop[(size_t)NL*DM*KP1];
__device__ __nv_bfloat16 g_w1p[(size_t)NL*DFF*KP1];
__device__ __nv_bfloat16 g_w2p[(size_t)NL*DM*KP2];
// fp16 transposed w_out [NV, DM]
__device__ __half g_wouth[(size_t)NV*DM];

// ---------------- PTX helpers ----------------
template<int DT>
__device__ __forceinline__ void mma_16816(float* d, const unsigned* a, const unsigned* b) {
    if constexpr (DT == 0) {
        asm volatile(
            "mma.sync.aligned.m16n8k16.row.col.f32.bf16.bf16.f32 "
            "{%0,%1,%2,%3}, {%4,%5,%6,%7}, {%8,%9}, {%0,%1,%2,%3};\n"
            : "+f"(d[0]), "+f"(d[1]), "+f"(d[2]), "+f"(d[3])
            : "r"(a[0]), "r"(a[1]), "r"(a[2]), "r"(a[3]), "r"(b[0]), "r"(b[1]));
    } else {
        asm volatile(
            "mma.sync.aligned.m16n8k16.row.col.f32.f16.f16.f32 "
            "{%0,%1,%2,%3}, {%4,%5,%6,%7}, {%8,%9}, {%0,%1,%2,%3};\n"
            : "+f"(d[0]), "+f"(d[1]), "+f"(d[2]), "+f"(d[3])
            : "r"(a[0]), "r"(a[1]), "r"(a[2]), "r"(a[3]), "r"(b[0]), "r"(b[1]));
    }
}
__device__ __forceinline__ void ldsm4(unsigned addr, unsigned& r0, unsigned& r1,
                                      unsigned& r2, unsigned& r3) {
    asm volatile("ldmatrix.sync.aligned.m8n8.x4.shared.b16 {%0,%1,%2,%3}, [%4];"
                 : "=r"(r0), "=r"(r1), "=r"(r2), "=r"(r3) : "r"(addr));
}
__device__ __forceinline__ void cpasync16(unsigned dst, const void* src, int srcbytes) {
    asm volatile("cp.async.cg.shared.global [%0], [%1], 16, %2;"
                 :: "r"(dst), "l"(src), "r"(srcbytes));
}
__device__ __forceinline__ void cp_commit() {
    asm volatile("cp.async.commit_group;" ::: "memory");
}
__device__ __forceinline__ void cp_wait0() {
    asm volatile("cp.async.wait_group 0;" ::: "memory");
}
__device__ __forceinline__ void cp_wait1() {
    asm volatile("cp.async.wait_group 1;" ::: "memory");
}
// A triple (hi, lo, hi); pairs with B triple (hi, hi, lo)
__device__ __forceinline__ unsigned short bf16bits(float v) {
    __nv_bfloat16 h = __float2bfloat16(v);
    return reinterpret_cast<unsigned short&>(h);
}
__device__ __forceinline__ float bf16val(unsigned short bits) {
    __nv_bfloat16 t = reinterpret_cast<__nv_bfloat16&>(bits);
    return __bfloat162float(t);
}
// A-pattern triples for an EVEN column pair (12 bytes, 3 x u32 stores)
__device__ __forceinline__ void store_triple2(__nv_bfloat16* p, float v0, float v1) {
    unsigned short h0 = bf16bits(v0);
    unsigned short l0 = bf16bits(v0 - bf16val(h0));
    unsigned short h1 = bf16bits(v1);
    unsigned short l1 = bf16bits(v1 - bf16val(h1));
    unsigned* q = reinterpret_cast<unsigned*>(p);
    q[0] = (unsigned)h0 | ((unsigned)l0 << 16);   // h0 l0
    q[1] = (unsigned)h0 | ((unsigned)h1 << 16);   // h0 h1
    q[2] = (unsigned)l1 | ((unsigned)h1 << 16);   // l1 h1
}
// B-pattern (hi,hi,lo) triples for a k pair (12 bytes, 3 x u32 stores)
__device__ __forceinline__ void store_btriple2(__nv_bfloat16* p, float v0, float v1) {
    unsigned short h0 = bf16bits(v0);
    unsigned short l0 = bf16bits(v0 - bf16val(h0));
    unsigned short h1 = bf16bits(v1);
    unsigned short l1 = bf16bits(v1 - bf16val(h1));
    unsigned* q = reinterpret_cast<unsigned*>(p);
    q[0] = (unsigned)h0 | ((unsigned)h0 << 16);   // h0 h0
    q[1] = (unsigned)l0 | ((unsigned)h1 << 16);   // l0 h1
    q[2] = (unsigned)h1 | ((unsigned)l1 << 16);   // h1 l1
}

// ---------------- merged weight pack: all 6 body weights ---------------------
// W[K,N] fp32 -> W'[N,3K] bf16 B-pattern triple. Pair-vectorized u32 stores.
__global__ void pack_all_kernel(const float* __restrict__ wq, const float* __restrict__ wk,
                                const float* __restrict__ wv, const float* __restrict__ wo,
                                const float* __restrict__ w1, const float* __restrict__ w2,
                                __nv_bfloat16* __restrict__ wqp, __nv_bfloat16* __restrict__ wkp,
                                __nv_bfloat16* __restrict__ wvp, __nv_bfloat16* __restrict__ wop,
                                __nv_bfloat16* __restrict__ w1p, __nv_bfloat16* __restrict__ w2p)
{
    __shared__ float sm[32][33];
    int bid = blockIdx.x;
    const float* W; __nv_bfloat16* Wp;
    int K, N, bx, by, layer;
    if (bid < 27648) {
        int wid = bid / 6912, rem = bid % 6912;
        layer = rem / 576; int rr = rem % 576;
        bx = rr % 24; by = rr / 24; K = DM; N = DM;
        W  = (wid == 0) ? wq  : (wid == 1) ? wk  : (wid == 2) ? wv  : wo;
        Wp = (wid == 0) ? wqp : (wid == 1) ? wkp : (wid == 2) ? wvp : wop;
    } else if (bid < 55296) {
        int rem = bid - 27648;
        layer = rem / 2304; int rr = rem % 2304;
        bx = rr % 96; by = rr / 96; K = DM; N = DFF;
        W = w1; Wp = w1p;
    } else {
        int rem = bid - 55296;
        layer = rem / 2304; int rr = rem % 2304;
        bx = rr % 24; by = rr / 24; K = DFF; N = DM;
        W = w2; Wp = w2p;
    }
    const size_t lw = (size_t)layer * K * N;
    const size_t lo = (size_t)layer * N * 3 * K;
    int n0 = bx * 32, k0 = by * 32;
    int tx = threadIdx.x, ty = threadIdx.y;   // 32 x 8
    int tid = ty * 32 + tx;                   // 0..255
#pragma unroll
    for (int j = 0; j < 4; j++) {
        int kk = ty + j * 8;
        sm[kk][tx] = W[lw + (size_t)(k0 + kk) * N + n0 + tx];
    }
    __syncthreads();
    // 512 pair-tasks: tau -> n = tau>>4, k-pair pr = tau&15
#pragma unroll
    for (int it = 0; it < 2; it++) {
        int tau = tid + it * 256;
        int n  = tau >> 4;
        int pr = tau & 15;
        float v0 = sm[2 * pr][n];
        float v1 = sm[2 * pr + 1][n];
        size_t o = lo + (size_t)(n0 + n) * (3 * K) + 3 * (k0 + 2 * pr);
        store_btriple2(Wp + o, v0, v1);
    }
}

// ---------------- w_out transpose: W[K,N] fp32 -> W'[N,K] fp16 (half2) -------
__global__ void packw_fp16_kernel(const float* __restrict__ W,
                                  __half* __restrict__ Wp, int K, int N)
{
    __shared__ float sm[32][33];
    int n0 = blockIdx.x * 32, k0 = blockIdx.y * 32;
    int tx = threadIdx.x, ty = threadIdx.y;
    int tid = ty * 32 + tx;
#pragma unroll
    for (int j = 0; j < 4; j++) {
        int kk = ty + j * 8;
        sm[kk][tx] = W[(size_t)(k0 + kk) * N + n0 + tx];
    }
    __syncthreads();
#pragma unroll
    for (int it = 0; it < 2; it++) {
        int tau = tid + it * 256;
        int n  = tau >> 4;
        int pr = tau & 15;
        float v0 = sm[2 * pr][n];
        float v1 = sm[2 * pr + 1][n];
        *reinterpret_cast<__half2*>(Wp + (size_t)(n0 + n) * K + k0 + 2 * pr) =
            __halves2half2(__float2half_rn(v0), __float2half_rn(v1));
    }
}

// ---------------- embedding + sinusoidal positional encoding ----------------
__global__ void embed_kernel(const int* __restrict__ idx,
                             const float* __restrict__ emb,
                             float* __restrict__ x)
{
    int i = blockIdx.x * blockDim.x + threadIdx.x;
    if (i >= MROWS * DM) return;
    int d  = i % DM;
    int bt = i / DM;
    int t  = bt % NT;
    int tok = idx[bt];
    int ii = d & ~1;
    float div = expf(-(float)ii * (logf(10000.0f) / (float)DM));
    float ang = (float)t * div;
    float pe  = (d & 1) ? cosf(ang) : sinf(ang);
    x[i] = emb[(size_t)tok * DM + d] + pe;
}

// ---------------- single-pass layernorm -> triple-packed bf16 ----------------
__global__ void __launch_bounds__(384)
ln_kernel(const float* __restrict__ x,
          const float* __restrict__ s,
          const float* __restrict__ b,
          __nv_bfloat16* __restrict__ yp)
{
    int row = blockIdx.x;
    int t   = threadIdx.x;               // 0..383
    const float* xr = x + (size_t)row * DM;
    float v0 = xr[2 * t], v1 = xr[2 * t + 1];

    __shared__ float r1[384], r2[384];
    r1[t] = v0 + v1;
    r2[t] = v0 * v0 + v1 * v1;
    __syncthreads();
    for (int o = 192; o >= 6; o >>= 1) {
        if (t < o) { r1[t] += r1[t + o]; r2[t] += r2[t + o]; }
        __syncthreads();
    }
    float mu  = (r1[0] + r1[1] + r1[2] + r1[3] + r1[4] + r1[5]) * (1.0f / DM);
    float ex2 = (r2[0] + r2[1] + r2[2] + r2[3] + r2[4] + r2[5]) * (1.0f / DM);
    float var = ex2 - mu * mu;
    float r = rsqrtf(var + 1e-5f);

    int c = 2 * t;
    float y0 = (v0 - mu) * r * s[c] + b[c];
    float y1 = (v1 - mu) * r * s[c + 1] + b[c + 1];
    store_triple2(yp + (size_t)row * KP1 + 3 * c, y0, y1);
}

// ---------------- single-pass final layernorm -> fp16 ------------------------
__global__ void __launch_bounds__(384)
ln_fp16_kernel(const float* __restrict__ x,
               const float* __restrict__ s,
               const float* __restrict__ b,
               __half* __restrict__ yh)
{
    int row = blockIdx.x;
    int t   = threadIdx.x;
    const float* xr = x + (size_t)row * DM;
    float v0 = xr[2 * t], v1 = xr[2 * t + 1];

    __shared__ float r1[384], r2[384];
    r1[t] = v0 + v1;
    r2[t] = v0 * v0 + v1 * v1;
    __syncthreads();
    for (int o = 192; o >= 6; o >>= 1) {
        if (t < o) { r1[t] += r1[t + o]; r2[t] += r2[t + o]; }
        __syncthreads();
    }
    float mu  = (r1[0] + r1[1] + r1[2] + r1[3] + r1[4] + r1[5]) * (1.0f / DM);
    float ex2 = (r2[0] + r2[1] + r2[2] + r2[3] + r2[4] + r2[5]) * (1.0f / DM);
    float var = ex2 - mu * mu;
    float r = rsqrtf(var + 1e-5f);

    int c = 2 * t;
    float y0 = (v0 - mu) * r * s[c] + b[c];
    float y1 = (v1 - mu) * r * s[c + 1] + b[c + 1];
    *reinterpret_cast<__half2*>(yh + (size_t)row * DM + c) =
        __halves2half2(__float2half_rn(y0), __float2half_rn(y1));
}

// ---------------- 16-bit mma.sync GEMM (bf16 or fp16) ------------------------
// EPI: 0 = +bias ; 1 = relu(+bias)->triple-pack ; 2 = +bias+R ;
//      4 = +bias, write C, AND per-row sum of exp(x-LM0) -> epart
struct GemmArgs3 {
    const __nv_bfloat16* B[3];
    float*               C[3];
    const float*         bias[3];
};

template<int BM, int BN, int MT, int NTT, int EPI, int DT>
__global__ void __launch_bounds__(256, 1)
mma_gemm(const __nv_bfloat16* __restrict__ A, GemmArgs3 ga,
         const float* __restrict__ R, __nv_bfloat16* __restrict__ P3,
         float* __restrict__ epart, int Ncols, int Kp)
{
    constexpr int BK = 64, ST = 72;
    constexpr int ROWS = BM + BN;
    constexpr int NCH  = ROWS * 8 / 256;
    extern __shared__ __align__(128) __nv_bfloat16 smem[];
    __shared__ float sm_es[4][BM];

    const int z = blockIdx.z;
    const __nv_bfloat16* __restrict__ Bg   = ga.B[z];
    float*               __restrict__ C    = ga.C[z];
    const float*         __restrict__ bias = ga.bias[z];

    const int tid  = threadIdx.x;
    const int lane = tid & 31;
    const int w    = tid >> 5;
    const int wr   = w >> 2;
    const int wc   = w & 3;
    const int row0 = blockIdx.x * BM;
    const int col0 = blockIdx.y * BN;
    const int mB   = wr * MT * 16;
    const int nB   = wc * NTT * 8;
    const unsigned sbase = (unsigned)__cvta_generic_to_shared(smem);

    float acc[MT][NTT][4];
#pragma unroll
    for (int i = 0; i < MT; i++)
#pragma unroll
        for (int j = 0; j < NTT; j++)
#pragma unroll
            for (int q = 0; q < 4; q++) acc[i][j][q] = 0.0f;

    auto load_stage = [&](int s, int k0) {
        unsigned dbase = sbase + (unsigned)(s * ROWS * ST) * 2;
#pragma unroll
        for (int i = 0; i < NCH; i++) {
            int ch  = tid + i * 256;
            int row = ch >> 3;
            int kq  = (ch & 7) * 8;
            const __nv_bfloat16* src;
            int bytes = 16;
            if (row < BM) {
                src = A + (size_t)(row0 + row) * Kp + k0 + kq;
            } else {
                int gn = col0 + row - BM;
                if (gn >= Ncols) { gn = Ncols - 1; bytes = 0; }
                src = Bg + (size_t)gn * Kp + k0 + kq;
            }
            cpasync16(dbase + (unsigned)(row * ST + kq) * 2, src, bytes);
        }
    };

    const int lrow  = lane & 15;
    const int lcolb = (lane >> 4) * 8;
    const int lrow8 = lane & 7;

    auto compute_stage = [&](int s) {
        unsigned base = sbase + (unsigned)(s * ROWS * ST) * 2;
#pragma unroll
        for (int ks = 0; ks < 4; ks++) {
            unsigned a[MT][4];
#pragma unroll
            for (int mt = 0; mt < MT; mt++) {
                unsigned off = (unsigned)((mB + mt * 16 + lrow) * ST + ks * 16 + lcolb) * 2;
                ldsm4(base + off, a[mt][0], a[mt][1], a[mt][2], a[mt][3]);
            }
            unsigned b[NTT][2];
            if constexpr (NTT == 3) {
                unsigned r0, r1, r2, r3;
                unsigned off0 = (unsigned)((BM + nB + lrow) * ST + ks * 16 + lcolb) * 2;
                ldsm4(base + off0, r0, r1, r2, r3);
                b[0][0] = r0; b[0][1] = r2;
                b[1][0] = r1; b[1][1] = r3;
                unsigned off1 = (unsigned)((BM + nB + 16 + lrow8) * ST + ks * 16 + lcolb) * 2;
                ldsm4(base + off1, r0, r1, r2, r3);
                b[2][0] = r0; b[2][1] = r2;
            } else {
#pragma unroll
                for (int np = 0; np < NTT / 2; np++) {
                    unsigned r0, r1, r2, r3;
                    unsigned off = (unsigned)((BM + nB + np * 16 + lrow) * ST + ks * 16 + lcolb) * 2;
                    ldsm4(base + off, r0, r1, r2, r3);
                    b[np * 2][0] = r0;     b[np * 2][1] = r2;
                    b[np * 2 + 1][0] = r1; b[np * 2 + 1][1] = r3;
                }
            }
#pragma unroll
            for (int mt = 0; mt < MT; mt++)
#pragma unroll
                for (int nt = 0; nt < NTT; nt++)
                    mma_16816<DT>(acc[mt][nt], a[mt], b[nt]);
        }
    };

    const int NIT = Kp / BK;
    load_stage(0, 0);  cp_commit();
    load_stage(1, BK); cp_commit();

#pragma unroll 1
    for (int it = 0; it < NIT; ++it) {
        if (it + 1 < NIT) cp_wait1(); else cp_wait0();
        __syncthreads();
        compute_stage(it % 3);
        if (it + 2 < NIT) { load_stage((it + 2) % 3, (it + 2) * BK); cp_commit(); }
    }

    // ---------------- epilogue ----------------
    const int grp = lane >> 2;
    const int tig = lane & 3;
#pragma unroll
    for (int mt = 0; mt < MT; mt++) {
        int r = row0 + mB + mt * 16 + grp;
        float e0 = 0.0f, e1 = 0.0f;
#pragma unroll
        for (int nt = 0; nt < NTT; nt++) {
            int c = col0 + nB + nt * 8 + tig * 2;
            if (c < Ncols) {
                float x0 = acc[mt][nt][0], x1 = acc[mt][nt][1];
                float x2 = acc[mt][nt][2], x3 = acc[mt][nt][3];
                if (bias) {
                    float b0 = bias[c], b1 = bias[c + 1];
                    x0 += b0; x1 += b1; x2 += b0; x3 += b1;
                }
                if (EPI == 1) {
                    x0 = fmaxf(x0, 0.f); x1 = fmaxf(x1, 0.f);
                    x2 = fmaxf(x2, 0.f); x3 = fmaxf(x3, 0.f);
                    size_t kp3 = 3 * (size_t)Ncols;
                    store_triple2(P3 + (size_t)r       * kp3 + 3 * c, x0, x1);
                    store_triple2(P3 + (size_t)(r + 8) * kp3 + 3 * c, x2, x3);
                } else {
                    if (EPI == 2) {
                        const float2 ra = *(const float2*)&R[(size_t)r       * Ncols + c];
                        const float2 rb = *(const float2*)&R[(size_t)(r + 8) * Ncols + c];
                        x0 += ra.x; x1 += ra.y; x2 += rb.x; x3 += rb.y;
                    }
                    if (EPI == 4) {
                        e0 += __expf(x0 - LM0) + __expf(x1 - LM0);
                        e1 += __expf(x2 - LM0) + __expf(x3 - LM0);
                    }
                    *(float2*)&C[(size_t)r       * Ncols + c] = make_float2(x0, x1);
                    *(float2*)&C[(size_t)(r + 8) * Ncols + c] = make_float2(x2, x3);
                }
            }
        }
        if constexpr (EPI == 4) {
            e0 += __shfl_xor_sync(0xffffffff, e0, 1);
            e0 += __shfl_xor_sync(0xffffffff, e0, 2);
            e1 += __shfl_xor_sync(0xffffffff, e1, 1);
            e1 += __shfl_xor_sync(0xffffffff, e1, 2);
            if (tig == 0) {
                sm_es[wc][mB + mt * 16 + grp]     = e0;
                sm_es[wc][mB + mt * 16 + grp + 8] = e1;
            }
        }
    }
    if constexpr (EPI == 4) {
        __syncthreads();
        if (tid < BM) {
            float es = sm_es[0][tid] + sm_es[1][tid] + sm_es[2][tid] + sm_es[3][tid];
            epart[(size_t)(row0 + tid) * gridDim.y + blockIdx.y] = es;
        }
    }
}

// ---------------- key-parallel tiled causal attention (round-11 proven) ------
// 512 threads (16 warps), warp = one query row; lane = one key per 32-key batch.
#define QR 16
__global__ void __launch_bounds__(512, 1)
attn_kernel(const float* __restrict__ q,
            const float* __restrict__ k,
            const float* __restrict__ v,
            __nv_bfloat16* __restrict__ op)
{
    __shared__ __align__(16) float kt[64 * 65];   // [d][key], pad 65
    __shared__ __align__(16) float vs[64 * 64];   // [key][d]

    const int tid  = threadIdx.x;
    const int wid  = tid >> 5;
    const int lane = tid & 31;
    const int qt0  = blockIdx.x * QR;
    const int h    = blockIdx.y;
    const int b    = blockIdx.z;
    const int t    = qt0 + wid;

    float qreg[64];
    size_t qb = ((size_t)(b * NT + t) * NH + h) * DH;
#pragma unroll
    for (int d = 0; d < 64; d += 4) {
        float4 qv = *(const float4*)&q[qb + d];
        qreg[d] = qv.x; qreg[d + 1] = qv.y; qreg[d + 2] = qv.z; qreg[d + 3] = qv.w;
    }

    float m = -INFINITY, l = 0.0f, o0 = 0.0f, o1 = 0.0f;
    const float scale = 0.125f;
    const int lr = tid >> 3;
    const int lc = (tid & 7) * 8;

    for (int s0 = 0; s0 <= qt0 + QR - 1; s0 += 64) {
        __syncthreads();
        {
            size_t gb = ((size_t)(b * NT + s0 + lr) * NH + h) * DH + lc;
            float4 k0 = *(const float4*)&k[gb];
            float4 k1 = *(const float4*)&k[gb + 4];
            kt[(lc + 0) * 65 + lr] = k0.x; kt[(lc + 1) * 65 + lr] = k0.y;
            kt[(lc + 2) * 65 + lr] = k0.z; kt[(lc + 3) * 65 + lr] = k0.w;
            kt[(lc + 4) * 65 + lr] = k1.x; kt[(lc + 5) * 65 + lr] = k1.y;
            kt[(lc + 6) * 65 + lr] = k1.z; kt[(lc + 7) * 65 + lr] = k1.w;
            *(float4*)&vs[lr * 64 + lc]     = *(const float4*)&v[gb];
            *(float4*)&vs[lr * 64 + lc + 4] = *(const float4*)&v[gb + 4];
        }
        __syncthreads();

        int nvalid = t - s0 + 1;
        if (nvalid > 64) nvalid = 64;
#pragma unroll 1
        for (int sb = 0; sb < nvalid; sb += 32) {
            int key = sb + lane;
            float sc = -INFINITY;
            if (key < nvalid) {
                float a = 0.0f;
#pragma unroll
                for (int d = 0; d < 64; d++)
                    a = fmaf(qreg[d], kt[d * 65 + key], a);
                sc = a * scale;
            }
            float mb = sc;
#pragma unroll
            for (int off = 16; off > 0; off >>= 1)
                mb = fmaxf(mb, __shfl_xor_sync(0xffffffff, mb, off));
            float mn = fmaxf(m, mb);
            float c  = __expf(m - mn);
            float p  = __expf(sc - mn);
            float ps = p;
#pragma unroll
            for (int off = 16; off > 0; off >>= 1)
                ps += __shfl_xor_sync(0xffffffff, ps, off);
            o0 *= c; o1 *= c;
            l = l * c + ps;
            m = mn;
#pragma unroll
            for (int i = 0; i < 32; i++) {
                float pi = __shfl_sync(0xffffffff, p, i);
                float2 vv = *(const float2*)&vs[(sb + i) * 64 + 2 * lane];
                o0 = fmaf(pi, vv.x, o0);
                o1 = fmaf(pi, vv.y, o1);
            }
        }
    }
    float inv = 1.0f / l;
    size_t tb = (size_t)(b * NT + t) * KP1 + 3 * (h * DH + 2 * lane);
    store_triple2(op + tb, o0 * inv, o1 * inv);
}

// ---------------- loss: gather partial exp-sums + target logit --------------
__global__ void loss_final_kernel(const float* __restrict__ partial,
                                  const float* __restrict__ logits,
                                  const int* __restrict__ tgt,
                                  float* __restrict__ rowloss)
{
    int r    = blockIdx.x * 8 + (threadIdx.x >> 5);
    int lane = threadIdx.x & 31;
    const float* pr = partial + (size_t)r * NCB;
    float s = 0.0f;
    for (int j = lane; j < NCB; j += 32) s += pr[j];
#pragma unroll
    for (int off = 16; off > 0; off >>= 1)
        s += __shfl_xor_sync(0xffffffff, s, off);
    if (lane == 0)
        rowloss[r] = LM0 + logf(s) - logits[(size_t)r * NV + tgt[r]];
}

__global__ void loss_reduce_kernel(const float* __restrict__ rowloss,
                                   float* __restrict__ out)
{
    __shared__ float sh[256];
    int tid = threadIdx.x;
    float s = 0.0f;
    for (int i = tid; i < MROWS; i += 256) s += rowloss[i];
    sh[tid] = s; __syncthreads();
    for (int o = 128; o > 0; o >>= 1) {
        if (tid < o) sh[tid] += sh[tid + o];
        __syncthreads();
    }
    if (tid == 0) out[0] = sh[0] * (1.0f / MROWS);
}

// ---------------- host driver ----------------
extern "C" void kernel_launch(void* const* d_in, const int* in_sizes, int n_in,
                              void* d_out, int out_size)
{
    const int*   idx     = (const int*)  d_in[0];
    const int*   targets = (const int*)  d_in[1];
    const float* emb     = (const float*)d_in[2];
    const float* wq      = (const float*)d_in[3];
    const float* wk      = (const float*)d_in[4];
    const float* wv      = (const float*)d_in[5];
    const float* wo      = (const float*)d_in[6];
    const float* bo      = (const float*)d_in[7];
    const float* ln1_s   = (const float*)d_in[8];
    const float* ln1_b   = (const float*)d_in[9];
    const float* ln2_s   = (const float*)d_in[10];
    const float* ln2_b   = (const float*)d_in[11];
    const float* w1      = (const float*)d_in[12];
    const float* b1      = (const float*)d_in[13];
    const float* w2      = (const float*)d_in[14];
    const float* b2      = (const float*)d_in[15];
    const float* lnf_s   = (const float*)d_in[16];
    const float* lnf_b   = (const float*)d_in[17];
    const float* w_out   = (const float*)d_in[18];
    const float* b_out   = (const float*)d_in[19];
    float* out = (float*)d_out;

    float *x, *q, *k, *v, *rl, *pt;
    __nv_bfloat16 *hp, *atp, *ffp, *wqp, *wkp, *wvp, *wop, *w1p, *w2p;
    __half *hf, *wouth;
    cudaGetSymbolAddress((void**)&x,     g_x);
    cudaGetSymbolAddress((void**)&q,     g_q);
    cudaGetSymbolAddress((void**)&k,     g_k);
    cudaGetSymbolAddress((void**)&v,     g_v);
    cudaGetSymbolAddress((void**)&rl,    g_rowloss);
    cudaGetSymbolAddress((void**)&pt,    g_partial);
    cudaGetSymbolAddress((void**)&hp,    g_hp);
    cudaGetSymbolAddress((void**)&atp,   g_atp);
    cudaGetSymbolAddress((void**)&ffp,   g_ffp);
    cudaGetSymbolAddress((void**)&hf,    g_hf);
    cudaGetSymbolAddress((void**)&wqp,   g_wqp);
    cudaGetSymbolAddress((void**)&wkp,   g_wkp);
    cudaGetSymbolAddress((void**)&wvp,   g_wvp);
    cudaGetSymbolAddress((void**)&wop,   g_wop);
    cudaGetSymbolAddress((void**)&w1p,   g_w1p);
    cudaGetSymbolAddress((void**)&w2p,   g_w2p);
    cudaGetSymbolAddress((void**)&wouth, g_wouth);

    const int SM_128 = 3 * (128 + 128) * 72 * 2;   // 110592
    const int SM_96  = 3 * (128 +  96) * 72 * 2;   //  96768
    const int SM_256 = 3 * (128 + 256) * 72 * 2;   // 165888
    cudaFuncSetAttribute(mma_gemm<128,128,4,4,0,0>, cudaFuncAttributeMaxDynamicSharedMemorySize, SM_128);
    cudaFuncSetAttribute(mma_gemm<128,128,4,4,1,0>, cudaFuncAttributeMaxDynamicSharedMemorySize, SM_128);
    cudaFuncSetAttribute(mma_gemm<128,96,4,3,2,0>,  cudaFuncAttributeMaxDynamicSharedMemorySize, SM_96);
    cudaFuncSetAttribute(mma_gemm<128,256,4,8,4,1>, cudaFuncAttributeMaxDynamicSharedMemorySize, SM_256);

    pack_all_kernel<<<82944, dim3(32, 8)>>>(wq, wk, wv, wo, w1, w2,
                                            wqp, wkp, wvp, wop, w1p, w2p);
    packw_fp16_kernel<<<dim3(NV / 32, DM / 32, 1), dim3(32, 8)>>>(w_out, wouth, DM, NV);
    embed_kernel<<<(MROWS * DM + 255) / 256, 256>>>(idx, emb, x);

    for (int l = 0; l < NL; l++) {
        size_t oq = (size_t)l * DM * KP1;
        size_t o1 = (size_t)l * DFF * KP1;
        size_t o2 = (size_t)l * DM * KP2;

        ln_kernel<<<MROWS, 384>>>(x, ln1_s + l * DM, ln1_b + l * DM, hp);

        {   // q,k,v = h @ w{q,k,v}
            GemmArgs3 ga = {};
            ga.B[0] = wqp + oq; ga.B[1] = wkp + oq; ga.B[2] = wvp + oq;
            ga.C[0] = q; ga.C[1] = k; ga.C[2] = v;
            mma_gemm<128,128,4,4,0,0><<<dim3(16, 6, 3), 256, SM_128>>>(
                hp, ga, nullptr, nullptr, nullptr, DM, KP1);
        }

        attn_kernel<<<dim3(NT / QR, NH, NB), 512>>>(q, k, v, atp);

        {   // x = x + att @ wo + bo
            GemmArgs3 ga = {};
            ga.B[0] = wop + oq; ga.C[0] = x; ga.bias[0] = bo + l * DM;
            mma_gemm<128,96,4,3,2,0><<<dim3(16, 8, 1), 256, SM_96>>>(
                atp, ga, x, nullptr, nullptr, DM, KP1);
        }

        ln_kernel<<<MROWS, 384>>>(x, ln2_s + l * DM, ln2_b + l * DM, hp);

        {   // ff = relu(h @ w1 + b1)
            GemmArgs3 ga = {};
            ga.B[0] = w1p + o1; ga.bias[0] = b1 + l * DFF;
            mma_gemm<128,128,4,4,1,0><<<dim3(16, 24, 1), 256, SM_128>>>(
                hp, ga, nullptr, ffp, nullptr, DFF, KP1);
        }

        {   // x = x + ff @ w2 + b2
            GemmArgs3 ga = {};
            ga.B[0] = w2p + o2; ga.C[0] = x; ga.bias[0] = b2 + l * DM;
            mma_gemm<128,96,4,3,2,0><<<dim3(16, 8, 1), 256, SM_96>>>(
                ffp, ga, x, nullptr, nullptr, DM, KP2);
        }
    }

    // h = LNf(x) -> fp16
    ln_fp16_kernel<<<MROWS, 384>>>(x, lnf_s, lnf_b, hf);

    // logits = h @ w_out + b_out, fused per-row exp-sum partials (EPI=4)
    {
        GemmArgs3 ga = {};
        ga.B[0] = (const __nv_bfloat16*)wouth;
        ga.C[0] = out; ga.bias[0] = b_out;
        mma_gemm<128,256,4,8,4,1><<<dim3(16, NCB, 1), 256, SM_256>>>(
            (const __nv_bfloat16*)hf, ga, nullptr, nullptr, pt, NV, DM);
    }

    // loss: gather partials + target logit, then mean
    loss_final_kernel<<<MROWS / 8, 256>>>(pt, out, targets, rl);
    loss_reduce_kernel<<<1, 256>>>(rl, out + (size_t)MROWS * NV);
}

// round 16
// speedup vs baseline: 1.0198x; 1.0032x over previous
#include <cuda_runtime.h>
#include <cuda_bf16.h>
#include <cuda_fp16.h>
#include <math.h>
#include <stdint.h>

// ---------------- problem constants ----------------
#define NL   12
#define NH   12
#define DM   768
#define DFF  3072
#define NV   100256
#define DH   64
#define NB   2
#define NT   1024
#define MROWS (NB*NT)          // 2048
#define KP1  (3*DM)            // 2304
#define KP2  (3*DFF)           // 9216
#define NCB  392               // logits col blocks = ceil(NV/256)
#define LM0  20.0f             // fixed log-sum-exp offset (|logits| << 20)

// ---------------- scratch (device globals; no allocs allowed) ----------------
__device__ float g_x[MROWS*DM];
__device__ float g_q[MROWS*DM];
__device__ float g_k[MROWS*DM];
__device__ float g_v[MROWS*DM];
__device__ float g_rowloss[MROWS];
__device__ float g_partial[(size_t)MROWS*NCB];
// triple-packed bf16 activations (A operands, body)
__device__ __nv_bfloat16 g_hp [MROWS*KP1];
__device__ __nv_bfloat16 g_atp[MROWS*KP1];
__device__ __nv_bfloat16 g_ffp[(size_t)MROWS*KP2];
// fp16 final-LN activations (logits A operand)
__device__ __half g_hf[MROWS*DM];
// triple-packed, transposed bf16 weights (body B operands, [N, 3K] K-major)
__device__ __nv_bfloat16 g_wqp[(size_t)NL*DM*KP1];
__device__ __nv_bfloat16 g_wkp[(size_t)NL*DM*KP1];
__device__ __nv_bfloat16 g_wvp[(size_t)NL*DM*KP1];
__device__ __nv_bfloat16 g_wop[(size_t)NL*DM*KP1];
__device__ __nv_bfloat16 g_w1p[(size_t)NL*DFF*KP1];
__device__ __nv_bfloat16 g_w2p[(size_t)NL*DM*KP2];
// fp16 transposed w_out [NV, DM]
__device__ __half g_wouth[(size_t)NV*DM];

// ---------------- PTX helpers ----------------
template<int DT>
__device__ __forceinline__ void mma_16816(float* d, const unsigned* a, const unsigned* b) {
    if constexpr (DT == 0) {
        asm volatile(
            "mma.sync.aligned.m16n8k16.row.col.f32.bf16.bf16.f32 "
            "{%0,%1,%2,%3}, {%4,%5,%6,%7}, {%8,%9}, {%0,%1,%2,%3};\n"
            : "+f"(d[0]), "+f"(d[1]), "+f"(d[2]), "+f"(d[3])
            : "r"(a[0]), "r"(a[1]), "r"(a[2]), "r"(a[3]), "r"(b[0]), "r"(b[1]));
    } else {
        asm volatile(
            "mma.sync.aligned.m16n8k16.row.col.f32.f16.f16.f32 "
            "{%0,%1,%2,%3}, {%4,%5,%6,%7}, {%8,%9}, {%0,%1,%2,%3};\n"
            : "+f"(d[0]), "+f"(d[1]), "+f"(d[2]), "+f"(d[3])
            : "r"(a[0]), "r"(a[1]), "r"(a[2]), "r"(a[3]), "r"(b[0]), "r"(b[1]));
    }
}
__device__ __forceinline__ void ldsm4(unsigned addr, unsigned& r0, unsigned& r1,
                                      unsigned& r2, unsigned& r3) {
    asm volatile("ldmatrix.sync.aligned.m8n8.x4.shared.b16 {%0,%1,%2,%3}, [%4];"
                 : "=r"(r0), "=r"(r1), "=r"(r2), "=r"(r3) : "r"(addr));
}
__device__ __forceinline__ void cpasync16(unsigned dst, const void* src, int srcbytes) {
    asm volatile("cp.async.cg.shared.global [%0], [%1], 16, %2;"
                 :: "r"(dst), "l"(src), "r"(srcbytes));
}
__device__ __forceinline__ void cp_commit() {
    asm volatile("cp.async.commit_group;" ::: "memory");
}
__device__ __forceinline__ void cp_wait0() {
    asm volatile("cp.async.wait_group 0;" ::: "memory");
}
__device__ __forceinline__ void cp_wait1() {
    asm volatile("cp.async.wait_group 1;" ::: "memory");
}
// A triple (hi, lo, hi); pairs with B triple (hi, hi, lo)
__device__ __forceinline__ unsigned short bf16bits(float v) {
    __nv_bfloat16 h = __float2bfloat16(v);
    return reinterpret_cast<unsigned short&>(h);
}
__device__ __forceinline__ float bf16val(unsigned short bits) {
    __nv_bfloat16 t = reinterpret_cast<__nv_bfloat16&>(bits);
    return __bfloat162float(t);
}
// A-pattern triples for an EVEN column pair (12 bytes, 3 x u32 stores)
__device__ __forceinline__ void store_triple2(__nv_bfloat16* p, float v0, float v1) {
    unsigned short h0 = bf16bits(v0);
    unsigned short l0 = bf16bits(v0 - bf16val(h0));
    unsigned short h1 = bf16bits(v1);
    unsigned short l1 = bf16bits(v1 - bf16val(h1));
    unsigned* q = reinterpret_cast<unsigned*>(p);
    q[0] = (unsigned)h0 | ((unsigned)l0 << 16);   // h0 l0
    q[1] = (unsigned)h0 | ((unsigned)h1 << 16);   // h0 h1
    q[2] = (unsigned)l1 | ((unsigned)h1 << 16);   // l1 h1
}
// B-pattern (hi,hi,lo) triples for a k pair (12 bytes, 3 x u32 stores)
__device__ __forceinline__ void store_btriple2(__nv_bfloat16* p, float v0, float v1) {
    unsigned short h0 = bf16bits(v0);
    unsigned short l0 = bf16bits(v0 - bf16val(h0));
    unsigned short h1 = bf16bits(v1);
    unsigned short l1 = bf16bits(v1 - bf16val(h1));
    unsigned* q = reinterpret_cast<unsigned*>(p);
    q[0] = (unsigned)h0 | ((unsigned)h0 << 16);   // h0 h0
    q[1] = (unsigned)l0 | ((unsigned)h1 << 16);   // l0 h1
    q[2] = (unsigned)h1 | ((unsigned)l1 << 16);   // h1 l1
}

// ---------------- merged weight pack: all 6 body weights ---------------------
// W[K,N] fp32 -> W'[N,3K] bf16 B-pattern triple. Pair-vectorized u32 stores.
__global__ void pack_all_kernel(const float* __restrict__ wq, const float* __restrict__ wk,
                                const float* __restrict__ wv, const float* __restrict__ wo,
                                const float* __restrict__ w1, const float* __restrict__ w2,
                                __nv_bfloat16* __restrict__ wqp, __nv_bfloat16* __restrict__ wkp,
                                __nv_bfloat16* __restrict__ wvp, __nv_bfloat16* __restrict__ wop,
                                __nv_bfloat16* __restrict__ w1p, __nv_bfloat16* __restrict__ w2p)
{
    __shared__ float sm[32][33];
    int bid = blockIdx.x;
    const float* W; __nv_bfloat16* Wp;
    int K, N, bx, by, layer;
    if (bid < 27648) {
        int wid = bid / 6912, rem = bid % 6912;
        layer = rem / 576; int rr = rem % 576;
        bx = rr % 24; by = rr / 24; K = DM; N = DM;
        W  = (wid == 0) ? wq  : (wid == 1) ? wk  : (wid == 2) ? wv  : wo;
        Wp = (wid == 0) ? wqp : (wid == 1) ? wkp : (wid == 2) ? wvp : wop;
    } else if (bid < 55296) {
        int rem = bid - 27648;
        layer = rem / 2304; int rr = rem % 2304;
        bx = rr % 96; by = rr / 96; K = DM; N = DFF;
        W = w1; Wp = w1p;
    } else {
        int rem = bid - 55296;
        layer = rem / 2304; int rr = rem % 2304;
        bx = rr % 24; by = rr / 24; K = DFF; N = DM;
        W = w2; Wp = w2p;
    }
    const size_t lw = (size_t)layer * K * N;
    const size_t lo = (size_t)layer * N * 3 * K;
    int n0 = bx * 32, k0 = by * 32;
    int tx = threadIdx.x, ty = threadIdx.y;   // 32 x 8
    int tid = ty * 32 + tx;                   // 0..255
#pragma unroll
    for (int j = 0; j < 4; j++) {
        int kk = ty + j * 8;
        sm[kk][tx] = W[lw + (size_t)(k0 + kk) * N + n0 + tx];
    }
    __syncthreads();
    // 512 pair-tasks: tau -> n = tau>>4, k-pair pr = tau&15
#pragma unroll
    for (int it = 0; it < 2; it++) {
        int tau = tid + it * 256;
        int n  = tau >> 4;
        int pr = tau & 15;
        float v0 = sm[2 * pr][n];
        float v1 = sm[2 * pr + 1][n];
        size_t o = lo + (size_t)(n0 + n) * (3 * K) + 3 * (k0 + 2 * pr);
        store_btriple2(Wp + o, v0, v1);
    }
}

// ---------------- w_out transpose: W[K,N] fp32 -> W'[N,K] fp16 (half2) -------
__global__ void packw_fp16_kernel(const float* __restrict__ W,
                                  __half* __restrict__ Wp, int K, int N)
{
    __shared__ float sm[32][33];
    int n0 = blockIdx.x * 32, k0 = blockIdx.y * 32;
    int tx = threadIdx.x, ty = threadIdx.y;
    int tid = ty * 32 + tx;
#pragma unroll
    for (int j = 0; j < 4; j++) {
        int kk = ty + j * 8;
        sm[kk][tx] = W[(size_t)(k0 + kk) * N + n0 + tx];
    }
    __syncthreads();
#pragma unroll
    for (int it = 0; it < 2; it++) {
        int tau = tid + it * 256;
        int n  = tau >> 4;
        int pr = tau & 15;
        float v0 = sm[2 * pr][n];
        float v1 = sm[2 * pr + 1][n];
        *reinterpret_cast<__half2*>(Wp + (size_t)(n0 + n) * K + k0 + 2 * pr) =
            __halves2half2(__float2half_rn(v0), __float2half_rn(v1));
    }
}

// ---------------- embedding + sinusoidal positional encoding ----------------
__global__ void embed_kernel(const int* __restrict__ idx,
                             const float* __restrict__ emb,
                             float* __restrict__ x)
{
    int i = blockIdx.x * blockDim.x + threadIdx.x;
    if (i >= MROWS * DM) return;
    int d  = i % DM;
    int bt = i / DM;
    int t  = bt % NT;
    int tok = idx[bt];
    int ii = d & ~1;
    float div = expf(-(float)ii * (logf(10000.0f) / (float)DM));
    float ang = (float)t * div;
    float pe  = (d & 1) ? cosf(ang) : sinf(ang);
    x[i] = emb[(size_t)tok * DM + d] + pe;
}

// ---------------- single-pass layernorm -> triple-packed bf16 ----------------
__global__ void __launch_bounds__(384)
ln_kernel(const float* __restrict__ x,
          const float* __restrict__ s,
          const float* __restrict__ b,
          __nv_bfloat16* __restrict__ yp)
{
    int row = blockIdx.x;
    int t   = threadIdx.x;               // 0..383
    const float* xr = x + (size_t)row * DM;
    float v0 = xr[2 * t], v1 = xr[2 * t + 1];

    __shared__ float r1[384], r2[384];
    r1[t] = v0 + v1;
    r2[t] = v0 * v0 + v1 * v1;
    __syncthreads();
    for (int o = 192; o >= 6; o >>= 1) {
        if (t < o) { r1[t] += r1[t + o]; r2[t] += r2[t + o]; }
        __syncthreads();
    }
    float mu  = (r1[0] + r1[1] + r1[2] + r1[3] + r1[4] + r1[5]) * (1.0f / DM);
    float ex2 = (r2[0] + r2[1] + r2[2] + r2[3] + r2[4] + r2[5]) * (1.0f / DM);
    float var = ex2 - mu * mu;
    float r = rsqrtf(var + 1e-5f);

    int c = 2 * t;
    float y0 = (v0 - mu) * r * s[c] + b[c];
    float y1 = (v1 - mu) * r * s[c + 1] + b[c + 1];
    store_triple2(yp + (size_t)row * KP1 + 3 * c, y0, y1);
}

// ---------------- single-pass final layernorm -> fp16 ------------------------
__global__ void __launch_bounds__(384)
ln_fp16_kernel(const float* __restrict__ x,
               const float* __restrict__ s,
               const float* __restrict__ b,
               __half* __restrict__ yh)
{
    int row = blockIdx.x;
    int t   = threadIdx.x;
    const float* xr = x + (size_t)row * DM;
    float v0 = xr[2 * t], v1 = xr[2 * t + 1];

    __shared__ float r1[384], r2[384];
    r1[t] = v0 + v1;
    r2[t] = v0 * v0 + v1 * v1;
    __syncthreads();
    for (int o = 192; o >= 6; o >>= 1) {
        if (t < o) { r1[t] += r1[t + o]; r2[t] += r2[t + o]; }
        __syncthreads();
    }
    float mu  = (r1[0] + r1[1] + r1[2] + r1[3] + r1[4] + r1[5]) * (1.0f / DM);
    float ex2 = (r2[0] + r2[1] + r2[2] + r2[3] + r2[4] + r2[5]) * (1.0f / DM);
    float var = ex2 - mu * mu;
    float r = rsqrtf(var + 1e-5f);

    int c = 2 * t;
    float y0 = (v0 - mu) * r * s[c] + b[c];
    float y1 = (v1 - mu) * r * s[c + 1] + b[c + 1];
    *reinterpret_cast<__half2*>(yh + (size_t)row * DM + c) =
        __halves2half2(__float2half_rn(y0), __float2half_rn(y1));
}

// ---------------- 16-bit mma.sync GEMM (bf16 or fp16) ------------------------
// EPI: 0 = +bias ; 1 = relu(+bias)->triple-pack ; 2 = +bias+R ;
//      4 = +bias, write C, AND per-row sum of exp(x-LM0) -> epart
struct GemmArgs3 {
    const __nv_bfloat16* B[3];
    float*               C[3];
    const float*         bias[3];
};

template<int BM, int BN, int MT, int NTT, int EPI, int DT>
__global__ void __launch_bounds__(256, 1)
mma_gemm(const __nv_bfloat16* __restrict__ A, GemmArgs3 ga,
         const float* __restrict__ R, __nv_bfloat16* __restrict__ P3,
         float* __restrict__ epart, int Ncols, int Kp)
{
    constexpr int BK = 64, ST = 72;
    constexpr int ROWS = BM + BN;
    constexpr int NCH  = ROWS * 8 / 256;
    extern __shared__ __align__(128) __nv_bfloat16 smem[];
    __shared__ float sm_es[4][BM];

    const int z = blockIdx.z;
    const __nv_bfloat16* __restrict__ Bg   = ga.B[z];
    float*               __restrict__ C    = ga.C[z];
    const float*         __restrict__ bias = ga.bias[z];

    const int tid  = threadIdx.x;
    const int lane = tid & 31;
    const int w    = tid >> 5;
    const int wr   = w >> 2;
    const int wc   = w & 3;
    const int row0 = blockIdx.x * BM;
    const int col0 = blockIdx.y * BN;
    const int mB   = wr * MT * 16;
    const int nB   = wc * NTT * 8;
    const unsigned sbase = (unsigned)__cvta_generic_to_shared(smem);

    float acc[MT][NTT][4];
#pragma unroll
    for (int i = 0; i < MT; i++)
#pragma unroll
        for (int j = 0; j < NTT; j++)
#pragma unroll
            for (int q = 0; q < 4; q++) acc[i][j][q] = 0.0f;

    auto load_stage = [&](int s, int k0) {
        unsigned dbase = sbase + (unsigned)(s * ROWS * ST) * 2;
#pragma unroll
        for (int i = 0; i < NCH; i++) {
            int ch  = tid + i * 256;
            int row = ch >> 3;
            int kq  = (ch & 7) * 8;
            const __nv_bfloat16* src;
            int bytes = 16;
            if (row < BM) {
                src = A + (size_t)(row0 + row) * Kp + k0 + kq;
            } else {
                int gn = col0 + row - BM;
                if (gn >= Ncols) { gn = Ncols - 1; bytes = 0; }
                src = Bg + (size_t)gn * Kp + k0 + kq;
            }
            cpasync16(dbase + (unsigned)(row * ST + kq) * 2, src, bytes);
        }
    };

    const int lrow  = lane & 15;
    const int lcolb = (lane >> 4) * 8;
    const int lrow8 = lane & 7;

    auto compute_stage = [&](int s) {
        unsigned base = sbase + (unsigned)(s * ROWS * ST) * 2;
#pragma unroll
        for (int ks = 0; ks < 4; ks++) {
            unsigned a[MT][4];
#pragma unroll
            for (int mt = 0; mt < MT; mt++) {
                unsigned off = (unsigned)((mB + mt * 16 + lrow) * ST + ks * 16 + lcolb) * 2;
                ldsm4(base + off, a[mt][0], a[mt][1], a[mt][2], a[mt][3]);
            }
            unsigned b[NTT][2];
            if constexpr (NTT == 3) {
                unsigned r0, r1, r2, r3;
                unsigned off0 = (unsigned)((BM + nB + lrow) * ST + ks * 16 + lcolb) * 2;
                ldsm4(base + off0, r0, r1, r2, r3);
                b[0][0] = r0; b[0][1] = r2;
                b[1][0] = r1; b[1][1] = r3;
                unsigned off1 = (unsigned)((BM + nB + 16 + lrow8) * ST + ks * 16 + lcolb) * 2;
                ldsm4(base + off1, r0, r1, r2, r3);
                b[2][0] = r0; b[2][1] = r2;
            } else {
#pragma unroll
                for (int np = 0; np < NTT / 2; np++) {
                    unsigned r0, r1, r2, r3;
                    unsigned off = (unsigned)((BM + nB + np * 16 + lrow) * ST + ks * 16 + lcolb) * 2;
                    ldsm4(base + off, r0, r1, r2, r3);
                    b[np * 2][0] = r0;     b[np * 2][1] = r2;
                    b[np * 2 + 1][0] = r1; b[np * 2 + 1][1] = r3;
                }
            }
#pragma unroll
            for (int mt = 0; mt < MT; mt++)
#pragma unroll
                for (int nt = 0; nt < NTT; nt++)
                    mma_16816<DT>(acc[mt][nt], a[mt], b[nt]);
        }
    };

    const int NIT = Kp / BK;
    load_stage(0, 0);  cp_commit();
    load_stage(1, BK); cp_commit();

#pragma unroll 1
    for (int it = 0; it < NIT; ++it) {
        if (it + 1 < NIT) cp_wait1(); else cp_wait0();
        __syncthreads();
        compute_stage(it % 3);
        if (it + 2 < NIT) { load_stage((it + 2) % 3, (it + 2) * BK); cp_commit(); }
    }

    // ---------------- epilogue ----------------
    const int grp = lane >> 2;
    const int tig = lane & 3;
#pragma unroll
    for (int mt = 0; mt < MT; mt++) {
        int r = row0 + mB + mt * 16 + grp;
        float e0 = 0.0f, e1 = 0.0f;
#pragma unroll
        for (int nt = 0; nt < NTT; nt++) {
            int c = col0 + nB + nt * 8 + tig * 2;
            if (c < Ncols) {
                float x0 = acc[mt][nt][0], x1 = acc[mt][nt][1];
                float x2 = acc[mt][nt][2], x3 = acc[mt][nt][3];
                if (bias) {
                    float b0 = bias[c], b1 = bias[c + 1];
                    x0 += b0; x1 += b1; x2 += b0; x3 += b1;
                }
                if (EPI == 1) {
                    x0 = fmaxf(x0, 0.f); x1 = fmaxf(x1, 0.f);
                    x2 = fmaxf(x2, 0.f); x3 = fmaxf(x3, 0.f);
                    size_t kp3 = 3 * (size_t)Ncols;
                    store_triple2(P3 + (size_t)r       * kp3 + 3 * c, x0, x1);
                    store_triple2(P3 + (size_t)(r + 8) * kp3 + 3 * c, x2, x3);
                } else {
                    if (EPI == 2) {
                        const float2 ra = *(const float2*)&R[(size_t)r       * Ncols + c];
                        const float2 rb = *(const float2*)&R[(size_t)(r + 8) * Ncols + c];
                        x0 += ra.x; x1 += ra.y; x2 += rb.x; x3 += rb.y;
                    }
                    if (EPI == 4) {
                        e0 += __expf(x0 - LM0) + __expf(x1 - LM0);
                        e1 += __expf(x2 - LM0) + __expf(x3 - LM0);
                    }
                    *(float2*)&C[(size_t)r       * Ncols + c] = make_float2(x0, x1);
                    *(float2*)&C[(size_t)(r + 8) * Ncols + c] = make_float2(x2, x3);
                }
            }
        }
        if constexpr (EPI == 4) {
            e0 += __shfl_xor_sync(0xffffffff, e0, 1);
            e0 += __shfl_xor_sync(0xffffffff, e0, 2);
            e1 += __shfl_xor_sync(0xffffffff, e1, 1);
            e1 += __shfl_xor_sync(0xffffffff, e1, 2);
            if (tig == 0) {
                sm_es[wc][mB + mt * 16 + grp]     = e0;
                sm_es[wc][mB + mt * 16 + grp + 8] = e1;
            }
        }
    }
    if constexpr (EPI == 4) {
        __syncthreads();
        if (tid < BM) {
            float es = sm_es[0][tid] + sm_es[1][tid] + sm_es[2][tid] + sm_es[3][tid];
            epart[(size_t)(row0 + tid) * gridDim.y + blockIdx.y] = es;
        }
    }
}

// ---------------- key-parallel tiled causal attention (round-11 proven) ------
// 512 threads (16 warps), warp = one query row; lane = one key per 32-key batch.
#define QR 16
__global__ void __launch_bounds__(512, 1)
attn_kernel(const float* __restrict__ q,
            const float* __restrict__ k,
            const float* __restrict__ v,
            __nv_bfloat16* __restrict__ op)
{
    __shared__ __align__(16) float kt[64 * 65];   // [d][key], pad 65
    __shared__ __align__(16) float vs[64 * 64];   // [key][d]

    const int tid  = threadIdx.x;
    const int wid  = tid >> 5;
    const int lane = tid & 31;
    const int qt0  = blockIdx.x * QR;
    const int h    = blockIdx.y;
    const int b    = blockIdx.z;
    const int t    = qt0 + wid;

    float qreg[64];
    size_t qb = ((size_t)(b * NT + t) * NH + h) * DH;
#pragma unroll
    for (int d = 0; d < 64; d += 4) {
        float4 qv = *(const float4*)&q[qb + d];
        qreg[d] = qv.x; qreg[d + 1] = qv.y; qreg[d + 2] = qv.z; qreg[d + 3] = qv.w;
    }

    float m = -INFINITY, l = 0.0f, o0 = 0.0f, o1 = 0.0f;
    const float scale = 0.125f;
    const int lr = tid >> 3;
    const int lc = (tid & 7) * 8;

    for (int s0 = 0; s0 <= qt0 + QR - 1; s0 += 64) {
        __syncthreads();
        {
            size_t gb = ((size_t)(b * NT + s0 + lr) * NH + h) * DH + lc;
            float4 k0 = *(const float4*)&k[gb];
            float4 k1 = *(const float4*)&k[gb + 4];
            kt[(lc + 0) * 65 + lr] = k0.x; kt[(lc + 1) * 65 + lr] = k0.y;
            kt[(lc + 2) * 65 + lr] = k0.z; kt[(lc + 3) * 65 + lr] = k0.w;
            kt[(lc + 4) * 65 + lr] = k1.x; kt[(lc + 5) * 65 + lr] = k1.y;
            kt[(lc + 6) * 65 + lr] = k1.z; kt[(lc + 7) * 65 + lr] = k1.w;
            *(float4*)&vs[lr * 64 + lc]     = *(const float4*)&v[gb];
            *(float4*)&vs[lr * 64 + lc + 4] = *(const float4*)&v[gb + 4];
        }
        __syncthreads();

        int nvalid = t - s0 + 1;
        if (nvalid > 64) nvalid = 64;
#pragma unroll 1
        for (int sb = 0; sb < nvalid; sb += 32) {
            int key = sb + lane;
            float sc = -INFINITY;
            if (key < nvalid) {
                float a = 0.0f;
#pragma unroll
                for (int d = 0; d < 64; d++)
                    a = fmaf(qreg[d], kt[d * 65 + key], a);
                sc = a * scale;
            }
            float mb = sc;
#pragma unroll
            for (int off = 16; off > 0; off >>= 1)
                mb = fmaxf(mb, __shfl_xor_sync(0xffffffff, mb, off));
            float mn = fmaxf(m, mb);
            float c  = __expf(m - mn);
            float p  = __expf(sc - mn);
            float ps = p;
#pragma unroll
            for (int off = 16; off > 0; off >>= 1)
                ps += __shfl_xor_sync(0xffffffff, ps, off);
            o0 *= c; o1 *= c;
            l = l * c + ps;
            m = mn;
#pragma unroll
            for (int i = 0; i < 32; i++) {
                float pi = __shfl_sync(0xffffffff, p, i);
                float2 vv = *(const float2*)&vs[(sb + i) * 64 + 2 * lane];
                o0 = fmaf(pi, vv.x, o0);
                o1 = fmaf(pi, vv.y, o1);
            }
        }
    }
    float inv = 1.0f / l;
    size_t tb = (size_t)(b * NT + t) * KP1 + 3 * (h * DH + 2 * lane);
    store_triple2(op + tb, o0 * inv, o1 * inv);
}

// ---------------- loss: gather partial exp-sums + target logit --------------
__global__ void loss_final_kernel(const float* __restrict__ partial,
                                  const float* __restrict__ logits,
                                  const int* __restrict__ tgt,
                                  float* __restrict__ rowloss)
{
    int r    = blockIdx.x * 8 + (threadIdx.x >> 5);
    int lane = threadIdx.x & 31;
    const float* pr = partial + (size_t)r * NCB;
    float s = 0.0f;
    for (int j = lane; j < NCB; j += 32) s += pr[j];
#pragma unroll
    for (int off = 16; off > 0; off >>= 1)
        s += __shfl_xor_sync(0xffffffff, s, off);
    if (lane == 0)
        rowloss[r] = LM0 + logf(s) - logits[(size_t)r * NV + tgt[r]];
}

__global__ void loss_reduce_kernel(const float* __restrict__ rowloss,
                                   float* __restrict__ out)
{
    __shared__ float sh[256];
    int tid = threadIdx.x;
    float s = 0.0f;
    for (int i = tid; i < MROWS; i += 256) s += rowloss[i];
    sh[tid] = s; __syncthreads();
    for (int o = 128; o > 0; o >>= 1) {
        if (tid < o) sh[tid] += sh[tid + o];
        __syncthreads();
    }
    if (tid == 0) out[0] = sh[0] * (1.0f / MROWS);
}

// ---------------- host driver ----------------
extern "C" void kernel_launch(void* const* d_in, const int* in_sizes, int n_in,
                              void* d_out, int out_size)
{
    const int*   idx     = (const int*)  d_in[0];
    const int*   targets = (const int*)  d_in[1];
    const float* emb     = (const float*)d_in[2];
    const float* wq      = (const float*)d_in[3];
    const float* wk      = (const float*)d_in[4];
    const float* wv      = (const float*)d_in[5];
    const float* wo      = (const float*)d_in[6];
    const float* bo      = (const float*)d_in[7];
    const float* ln1_s   = (const float*)d_in[8];
    const float* ln1_b   = (const float*)d_in[9];
    const float* ln2_s   = (const float*)d_in[10];
    const float* ln2_b   = (const float*)d_in[11];
    const float* w1      = (const float*)d_in[12];
    const float* b1      = (const float*)d_in[13];
    const float* w2      = (const float*)d_in[14];
    const float* b2      = (const float*)d_in[15];
    const float* lnf_s   = (const float*)d_in[16];
    const float* lnf_b   = (const float*)d_in[17];
    const float* w_out   = (const float*)d_in[18];
    const float* b_out   = (const float*)d_in[19];
    float* out = (float*)d_out;

    float *x, *q, *k, *v, *rl, *pt;
    __nv_bfloat16 *hp, *atp, *ffp, *wqp, *wkp, *wvp, *wop, *w1p, *w2p;
    __half *hf, *wouth;
    cudaGetSymbolAddress((void**)&x,     g_x);
    cudaGetSymbolAddress((void**)&q,     g_q);
    cudaGetSymbolAddress((void**)&k,     g_k);
    cudaGetSymbolAddress((void**)&v,     g_v);
    cudaGetSymbolAddress((void**)&rl,    g_rowloss);
    cudaGetSymbolAddress((void**)&pt,    g_partial);
    cudaGetSymbolAddress((void**)&hp,    g_hp);
    cudaGetSymbolAddress((void**)&atp,   g_atp);
    cudaGetSymbolAddress((void**)&ffp,   g_ffp);
    cudaGetSymbolAddress((void**)&hf,    g_hf);
    cudaGetSymbolAddress((void**)&wqp,   g_wqp);
    cudaGetSymbolAddress((void**)&wkp,   g_wkp);
    cudaGetSymbolAddress((void**)&wvp,   g_wvp);
    cudaGetSymbolAddress((void**)&wop,   g_wop);
    cudaGetSymbolAddress((void**)&w1p,   g_w1p);
    cudaGetSymbolAddress((void**)&w2p,   g_w2p);
    cudaGetSymbolAddress((void**)&wouth, g_wouth);

    const int SM_128 = 3 * (128 + 128) * 72 * 2;   // 110592
    const int SM_96  = 3 * (128 +  96) * 72 * 2;   //  96768
    const int SM_256 = 3 * (128 + 256) * 72 * 2;   // 165888
    cudaFuncSetAttribute(mma_gemm<128,128,4,4,0,0>, cudaFuncAttributeMaxDynamicSharedMemorySize, SM_128);
    cudaFuncSetAttribute(mma_gemm<128,128,4,4,1,0>, cudaFuncAttributeMaxDynamicSharedMemorySize, SM_128);
    cudaFuncSetAttribute(mma_gemm<128,96,4,3,2,0>,  cudaFuncAttributeMaxDynamicSharedMemorySize, SM_96);
    cudaFuncSetAttribute(mma_gemm<128,256,4,8,4,1>, cudaFuncAttributeMaxDynamicSharedMemorySize, SM_256);

    pack_all_kernel<<<82944, dim3(32, 8)>>>(wq, wk, wv, wo, w1, w2,
                                            wqp, wkp, wvp, wop, w1p, w2p);
    packw_fp16_kernel<<<dim3(NV / 32, DM / 32, 1), dim3(32, 8)>>>(w_out, wouth, DM, NV);
    embed_kernel<<<(MROWS * DM + 255) / 256, 256>>>(idx, emb, x);

    for (int l = 0; l < NL; l++) {
        size_t oq = (size_t)l * DM * KP1;
        size_t o1 = (size_t)l * DFF * KP1;
        size_t o2 = (size_t)l * DM * KP2;

        ln_kernel<<<MROWS, 384>>>(x, ln1_s + l * DM, ln1_b + l * DM, hp);

        {   // q,k,v = h @ w{q,k,v}
            GemmArgs3 ga = {};
            ga.B[0] = wqp + oq; ga.B[1] = wkp + oq; ga.B[2] = wvp + oq;
            ga.C[0] = q; ga.C[1] = k; ga.C[2] = v;
            mma_gemm<128,128,4,4,0,0><<<dim3(16, 6, 3), 256, SM_128>>>(
                hp, ga, nullptr, nullptr, nullptr, DM, KP1);
        }

        attn_kernel<<<dim3(NT / QR, NH, NB), 512>>>(q, k, v, atp);

        {   // x = x + att @ wo + bo
            GemmArgs3 ga = {};
            ga.B[0] = wop + oq; ga.C[0] = x; ga.bias[0] = bo + l * DM;
            mma_gemm<128,96,4,3,2,0><<<dim3(16, 8, 1), 256, SM_96>>>(
                atp, ga, x, nullptr, nullptr, DM, KP1);
        }

        ln_kernel<<<MROWS, 384>>>(x, ln2_s + l * DM, ln2_b + l * DM, hp);

        {   // ff = relu(h @ w1 + b1)
            GemmArgs3 ga = {};
            ga.B[0] = w1p + o1; ga.bias[0] = b1 + l * DFF;
            mma_gemm<128,128,4,4,1,0><<<dim3(16, 24, 1), 256, SM_128>>>(
                hp, ga, nullptr, ffp, nullptr, DFF, KP1);
        }

        {   // x = x + ff @ w2 + b2
            GemmArgs3 ga = {};
            ga.B[0] = w2p + o2; ga.C[0] = x; ga.bias[0] = b2 + l * DM;
            mma_gemm<128,96,4,3,2,0><<<dim3(16, 8, 1), 256, SM_96>>>(
                ffp, ga, x, nullptr, nullptr, DM, KP2);
        }
    }

    // h = LNf(x) -> fp16
    ln_fp16_kernel<<<MROWS, 384>>>(x, lnf_s, lnf_b, hf);

    // logits = h @ w_out + b_out, fused per-row exp-sum partials (EPI=4)
    {
        GemmArgs3 ga = {};
        ga.B[0] = (const __nv_bfloat16*)wouth;
        ga.C[0] = out; ga.bias[0] = b_out;
        mma_gemm<128,256,4,8,4,1><<<dim3(16, NCB, 1), 256, SM_256>>>(
            (const __nv_bfloat16*)hf, ga, nullptr, nullptr, pt, NV, DM);
    }

    // loss: gather partials + target logit, then mean
    loss_final_kernel<<<MROWS / 8, 256>>>(pt, out, targets, rl);
    loss_reduce_kernel<<<1, 256>>>(rl, out + (size_t)MROWS * NV);
}

// round 17
// speedup vs baseline: 1.0220x; 1.0021x over previous
#include <cuda_runtime.h>
#include <cuda_bf16.h>
#include <cuda_fp16.h>
#include <math.h>
#include <stdint.h>

// ---------------- problem constants ----------------
#define NL   12
#define NH   12
#define DM   768
#define DFF  3072
#define NV   100256
#define DH   64
#define NB   2
#define NT   1024
#define MROWS (NB*NT)          // 2048
#define KP1  (3*DM)            // 2304
#define KP2  (3*DFF)           // 9216
#define NCB  392               // logits col blocks = ceil(NV/256)
#define LM0  20.0f             // fixed log-sum-exp offset (|logits| << 20)

// ---------------- scratch (device globals; no allocs allowed) ----------------
__device__ float g_x[MROWS*DM];
__device__ float g_q[MROWS*DM];
__device__ float g_k[MROWS*DM];
__device__ float g_v[MROWS*DM];
__device__ float g_rowloss[MROWS];
__device__ float g_partial[(size_t)MROWS*NCB];
// triple-packed bf16 activations (A operands, body)
__device__ __nv_bfloat16 g_hp [MROWS*KP1];
__device__ __nv_bfloat16 g_atp[MROWS*KP1];
__device__ __nv_bfloat16 g_ffp[(size_t)MROWS*KP2];
// fp16 final-LN activations (logits A operand)
__device__ __half g_hf[MROWS*DM];
// triple-packed, transposed bf16 weights (body B operands, [N, 3K] K-major)
__device__ __nv_bfloat16 g_wqp[(size_t)NL*DM*KP1];
__device__ __nv_bfloat16 g_wkp[(size_t)NL*DM*KP1];
__device__ __nv_bfloat16 g_wvp[(size_t)NL*DM*KP1];
__device__ __nv_bfloat16 g_wop[(size_t)NL*DM*KP1];
__device__ __nv_bfloat16 g_w1p[(size_t)NL*DFF*KP1];
__device__ __nv_bfloat16 g_w2p[(size_t)NL*DM*KP2];
// fp16 transposed w_out [NV, DM]
__device__ __half g_wouth[(size_t)NV*DM];

// ---------------- PTX helpers ----------------
template<int DT>
__device__ __forceinline__ void mma_16816(float* d, const unsigned* a, const unsigned* b) {
    if constexpr (DT == 0) {
        asm volatile(
            "mma.sync.aligned.m16n8k16.row.col.f32.bf16.bf16.f32 "
            "{%0,%1,%2,%3}, {%4,%5,%6,%7}, {%8,%9}, {%0,%1,%2,%3};\n"
            : "+f"(d[0]), "+f"(d[1]), "+f"(d[2]), "+f"(d[3])
            : "r"(a[0]), "r"(a[1]), "r"(a[2]), "r"(a[3]), "r"(b[0]), "r"(b[1]));
    } else {
        asm volatile(
            "mma.sync.aligned.m16n8k16.row.col.f32.f16.f16.f32 "
            "{%0,%1,%2,%3}, {%4,%5,%6,%7}, {%8,%9}, {%0,%1,%2,%3};\n"
            : "+f"(d[0]), "+f"(d[1]), "+f"(d[2]), "+f"(d[3])
            : "r"(a[0]), "r"(a[1]), "r"(a[2]), "r"(a[3]), "r"(b[0]), "r"(b[1]));
    }
}
__device__ __forceinline__ void ldsm4(unsigned addr, unsigned& r0, unsigned& r1,
                                      unsigned& r2, unsigned& r3) {
    asm volatile("ldmatrix.sync.aligned.m8n8.x4.shared.b16 {%0,%1,%2,%3}, [%4];"
                 : "=r"(r0), "=r"(r1), "=r"(r2), "=r"(r3) : "r"(addr));
}
__device__ __forceinline__ void cpasync16(unsigned dst, const void* src, int srcbytes) {
    asm volatile("cp.async.cg.shared.global [%0], [%1], 16, %2;"
                 :: "r"(dst), "l"(src), "r"(srcbytes));
}
__device__ __forceinline__ void cp_commit() {
    asm volatile("cp.async.commit_group;" ::: "memory");
}
__device__ __forceinline__ void cp_wait0() {
    asm volatile("cp.async.wait_group 0;" ::: "memory");
}
__device__ __forceinline__ void cp_wait1() {
    asm volatile("cp.async.wait_group 1;" ::: "memory");
}
// A triple (hi, lo, hi); pairs with B triple (hi, hi, lo)
__device__ __forceinline__ unsigned short bf16bits(float v) {
    __nv_bfloat16 h = __float2bfloat16(v);
    return reinterpret_cast<unsigned short&>(h);
}
__device__ __forceinline__ float bf16val(unsigned short bits) {
    __nv_bfloat16 t = reinterpret_cast<__nv_bfloat16&>(bits);
    return __bfloat162float(t);
}
// A-pattern triples for an EVEN column pair (12 bytes, 3 x u32 stores)
__device__ __forceinline__ void store_triple2(__nv_bfloat16* p, float v0, float v1) {
    unsigned short h0 = bf16bits(v0);
    unsigned short l0 = bf16bits(v0 - bf16val(h0));
    unsigned short h1 = bf16bits(v1);
    unsigned short l1 = bf16bits(v1 - bf16val(h1));
    unsigned* q = reinterpret_cast<unsigned*>(p);
    q[0] = (unsigned)h0 | ((unsigned)l0 << 16);   // h0 l0
    q[1] = (unsigned)h0 | ((unsigned)h1 << 16);   // h0 h1
    q[2] = (unsigned)l1 | ((unsigned)h1 << 16);   // l1 h1
}
// B-pattern (hi,hi,lo) triples for a k pair (12 bytes, 3 x u32 stores)
__device__ __forceinline__ void store_btriple2(__nv_bfloat16* p, float v0, float v1) {
    unsigned short h0 = bf16bits(v0);
    unsigned short l0 = bf16bits(v0 - bf16val(h0));
    unsigned short h1 = bf16bits(v1);
    unsigned short l1 = bf16bits(v1 - bf16val(h1));
    unsigned* q = reinterpret_cast<unsigned*>(p);
    q[0] = (unsigned)h0 | ((unsigned)h0 << 16);   // h0 h0
    q[1] = (unsigned)l0 | ((unsigned)h1 << 16);   // l0 h1
    q[2] = (unsigned)h1 | ((unsigned)l1 << 16);   // h1 l1
}

// ---------------- merged weight pack: all 6 body weights ---------------------
// W[K,N] fp32 -> W'[N,3K] bf16 B-pattern triple. Pair-vectorized u32 stores.
__global__ void pack_all_kernel(const float* __restrict__ wq, const float* __restrict__ wk,
                                const float* __restrict__ wv, const float* __restrict__ wo,
                                const float* __restrict__ w1, const float* __restrict__ w2,
                                __nv_bfloat16* __restrict__ wqp, __nv_bfloat16* __restrict__ wkp,
                                __nv_bfloat16* __restrict__ wvp, __nv_bfloat16* __restrict__ wop,
                                __nv_bfloat16* __restrict__ w1p, __nv_bfloat16* __restrict__ w2p)
{
    __shared__ float sm[32][33];
    int bid = blockIdx.x;
    const float* W; __nv_bfloat16* Wp;
    int K, N, bx, by, layer;
    if (bid < 27648) {
        int wid = bid / 6912, rem = bid % 6912;
        layer = rem / 576; int rr = rem % 576;
        bx = rr % 24; by = rr / 24; K = DM; N = DM;
        W  = (wid == 0) ? wq  : (wid == 1) ? wk  : (wid == 2) ? wv  : wo;
        Wp = (wid == 0) ? wqp : (wid == 1) ? wkp : (wid == 2) ? wvp : wop;
    } else if (bid < 55296) {
        int rem = bid - 27648;
        layer = rem / 2304; int rr = rem % 2304;
        bx = rr % 96; by = rr / 96; K = DM; N = DFF;
        W = w1; Wp = w1p;
    } else {
        int rem = bid - 55296;
        layer = rem / 2304; int rr = rem % 2304;
        bx = rr % 24; by = rr / 24; K = DFF; N = DM;
        W = w2; Wp = w2p;
    }
    const size_t lw = (size_t)layer * K * N;
    const size_t lo = (size_t)layer * N * 3 * K;
    int n0 = bx * 32, k0 = by * 32;
    int tx = threadIdx.x, ty = threadIdx.y;   // 32 x 8
    int tid = ty * 32 + tx;                   // 0..255
#pragma unroll
    for (int j = 0; j < 4; j++) {
        int kk = ty + j * 8;
        sm[kk][tx] = W[lw + (size_t)(k0 + kk) * N + n0 + tx];
    }
    __syncthreads();
    // 512 pair-tasks: tau -> n = tau>>4, k-pair pr = tau&15
#pragma unroll
    for (int it = 0; it < 2; it++) {
        int tau = tid + it * 256;
        int n  = tau >> 4;
        int pr = tau & 15;
        float v0 = sm[2 * pr][n];
        float v1 = sm[2 * pr + 1][n];
        size_t o = lo + (size_t)(n0 + n) * (3 * K) + 3 * (k0 + 2 * pr);
        store_btriple2(Wp + o, v0, v1);
    }
}

// ---------------- w_out transpose: W[K,N] fp32 -> W'[N,K] fp16 (half2) -------
__global__ void packw_fp16_kernel(const float* __restrict__ W,
                                  __half* __restrict__ Wp, int K, int N)
{
    __shared__ float sm[32][33];
    int n0 = blockIdx.x * 32, k0 = blockIdx.y * 32;
    int tx = threadIdx.x, ty = threadIdx.y;
    int tid = ty * 32 + tx;
#pragma unroll
    for (int j = 0; j < 4; j++) {
        int kk = ty + j * 8;
        sm[kk][tx] = W[(size_t)(k0 + kk) * N + n0 + tx];
    }
    __syncthreads();
#pragma unroll
    for (int it = 0; it < 2; it++) {
        int tau = tid + it * 256;
        int n  = tau >> 4;
        int pr = tau & 15;
        float v0 = sm[2 * pr][n];
        float v1 = sm[2 * pr + 1][n];
        *reinterpret_cast<__half2*>(Wp + (size_t)(n0 + n) * K + k0 + 2 * pr) =
            __halves2half2(__float2half_rn(v0), __float2half_rn(v1));
    }
}

// ---------------- embedding + sinusoidal positional encoding ----------------
__global__ void embed_kernel(const int* __restrict__ idx,
                             const float* __restrict__ emb,
                             float* __restrict__ x)
{
    int i = blockIdx.x * blockDim.x + threadIdx.x;
    if (i >= MROWS * DM) return;
    int d  = i % DM;
    int bt = i / DM;
    int t  = bt % NT;
    int tok = idx[bt];
    int ii = d & ~1;
    float div = expf(-(float)ii * (logf(10000.0f) / (float)DM));
    float ang = (float)t * div;
    float pe  = (d & 1) ? cosf(ang) : sinf(ang);
    x[i] = emb[(size_t)tok * DM + d] + pe;
}

// ---------------- single-pass layernorm -> triple-packed bf16 ----------------
__global__ void __launch_bounds__(384)
ln_kernel(const float* __restrict__ x,
          const float* __restrict__ s,
          const float* __restrict__ b,
          __nv_bfloat16* __restrict__ yp)
{
    int row = blockIdx.x;
    int t   = threadIdx.x;               // 0..383
    const float* xr = x + (size_t)row * DM;
    float v0 = xr[2 * t], v1 = xr[2 * t + 1];

    __shared__ float r1[384], r2[384];
    r1[t] = v0 + v1;
    r2[t] = v0 * v0 + v1 * v1;
    __syncthreads();
    for (int o = 192; o >= 6; o >>= 1) {
        if (t < o) { r1[t] += r1[t + o]; r2[t] += r2[t + o]; }
        __syncthreads();
    }
    float mu  = (r1[0] + r1[1] + r1[2] + r1[3] + r1[4] + r1[5]) * (1.0f / DM);
    float ex2 = (r2[0] + r2[1] + r2[2] + r2[3] + r2[4] + r2[5]) * (1.0f / DM);
    float var = ex2 - mu * mu;
    float r = rsqrtf(var + 1e-5f);

    int c = 2 * t;
    float y0 = (v0 - mu) * r * s[c] + b[c];
    float y1 = (v1 - mu) * r * s[c + 1] + b[c + 1];
    store_triple2(yp + (size_t)row * KP1 + 3 * c, y0, y1);
}

// ---------------- single-pass final layernorm -> fp16 ------------------------
__global__ void __launch_bounds__(384)
ln_fp16_kernel(const float* __restrict__ x,
               const float* __restrict__ s,
               const float* __restrict__ b,
               __half* __restrict__ yh)
{
    int row = blockIdx.x;
    int t   = threadIdx.x;
    const float* xr = x + (size_t)row * DM;
    float v0 = xr[2 * t], v1 = xr[2 * t + 1];

    __shared__ float r1[384], r2[384];
    r1[t] = v0 + v1;
    r2[t] = v0 * v0 + v1 * v1;
    __syncthreads();
    for (int o = 192; o >= 6; o >>= 1) {
        if (t < o) { r1[t] += r1[t + o]; r2[t] += r2[t + o]; }
        __syncthreads();
    }
    float mu  = (r1[0] + r1[1] + r1[2] + r1[3] + r1[4] + r1[5]) * (1.0f / DM);
    float ex2 = (r2[0] + r2[1] + r2[2] + r2[3] + r2[4] + r2[5]) * (1.0f / DM);
    float var = ex2 - mu * mu;
    float r = rsqrtf(var + 1e-5f);

    int c = 2 * t;
    float y0 = (v0 - mu) * r * s[c] + b[c];
    float y1 = (v1 - mu) * r * s[c + 1] + b[c + 1];
    *reinterpret_cast<__half2*>(yh + (size_t)row * DM + c) =
        __halves2half2(__float2half_rn(y0), __float2half_rn(y1));
}

// ---------------- 16-bit mma.sync GEMM (bf16 or fp16) ------------------------
// EPI: 0 = +bias ; 1 = relu(+bias)->triple-pack ; 2 = +bias+R ;
//      4 = +bias, write C, AND per-row sum of exp(x-LM0) -> epart
struct GemmArgs3 {
    const __nv_bfloat16* B[3];
    float*               C[3];
    const float*         bias[3];
};

template<int BM, int BN, int MT, int NTT, int EPI, int DT>
__global__ void __launch_bounds__(256, 1)
mma_gemm(const __nv_bfloat16* __restrict__ A, GemmArgs3 ga,
         const float* __restrict__ R, __nv_bfloat16* __restrict__ P3,
         float* __restrict__ epart, int Ncols, int Kp)
{
    constexpr int BK = 64, ST = 72;
    constexpr int ROWS = BM + BN;
    constexpr int NCH  = ROWS * 8 / 256;
    extern __shared__ __align__(128) __nv_bfloat16 smem[];
    __shared__ float sm_es[4][BM];

    const int z = blockIdx.z;
    const __nv_bfloat16* __restrict__ Bg   = ga.B[z];
    float*               __restrict__ C    = ga.C[z];
    const float*         __restrict__ bias = ga.bias[z];

    const int tid  = threadIdx.x;
    const int lane = tid & 31;
    const int w    = tid >> 5;
    const int wr   = w >> 2;
    const int wc   = w & 3;
    const int row0 = blockIdx.x * BM;
    const int col0 = blockIdx.y * BN;
    const int mB   = wr * MT * 16;
    const int nB   = wc * NTT * 8;
    const unsigned sbase = (unsigned)__cvta_generic_to_shared(smem);

    float acc[MT][NTT][4];
#pragma unroll
    for (int i = 0; i < MT; i++)
#pragma unroll
        for (int j = 0; j < NTT; j++)
#pragma unroll
            for (int q = 0; q < 4; q++) acc[i][j][q] = 0.0f;

    auto load_stage = [&](int s, int k0) {
        unsigned dbase = sbase + (unsigned)(s * ROWS * ST) * 2;
#pragma unroll
        for (int i = 0; i < NCH; i++) {
            int ch  = tid + i * 256;
            int row = ch >> 3;
            int kq  = (ch & 7) * 8;
            const __nv_bfloat16* src;
            int bytes = 16;
            if (row < BM) {
                src = A + (size_t)(row0 + row) * Kp + k0 + kq;
            } else {
                int gn = col0 + row - BM;
                if (gn >= Ncols) { gn = Ncols - 1; bytes = 0; }
                src = Bg + (size_t)gn * Kp + k0 + kq;
            }
            cpasync16(dbase + (unsigned)(row * ST + kq) * 2, src, bytes);
        }
    };

    const int lrow  = lane & 15;
    const int lcolb = (lane >> 4) * 8;
    const int lrow8 = lane & 7;

    auto compute_stage = [&](int s) {
        unsigned base = sbase + (unsigned)(s * ROWS * ST) * 2;
#pragma unroll
        for (int ks = 0; ks < 4; ks++) {
            unsigned a[MT][4];
#pragma unroll
            for (int mt = 0; mt < MT; mt++) {
                unsigned off = (unsigned)((mB + mt * 16 + lrow) * ST + ks * 16 + lcolb) * 2;
                ldsm4(base + off, a[mt][0], a[mt][1], a[mt][2], a[mt][3]);
            }
            unsigned b[NTT][2];
            if constexpr (NTT == 3) {
                unsigned r0, r1, r2, r3;
                unsigned off0 = (unsigned)((BM + nB + lrow) * ST + ks * 16 + lcolb) * 2;
                ldsm4(base + off0, r0, r1, r2, r3);
                b[0][0] = r0; b[0][1] = r2;
                b[1][0] = r1; b[1][1] = r3;
                unsigned off1 = (unsigned)((BM + nB + 16 + lrow8) * ST + ks * 16 + lcolb) * 2;
                ldsm4(base + off1, r0, r1, r2, r3);
                b[2][0] = r0; b[2][1] = r2;
            } else {
#pragma unroll
                for (int np = 0; np < NTT / 2; np++) {
                    unsigned r0, r1, r2, r3;
                    unsigned off = (unsigned)((BM + nB + np * 16 + lrow) * ST + ks * 16 + lcolb) * 2;
                    ldsm4(base + off, r0, r1, r2, r3);
                    b[np * 2][0] = r0;     b[np * 2][1] = r2;
                    b[np * 2 + 1][0] = r1; b[np * 2 + 1][1] = r3;
                }
            }
#pragma unroll
            for (int mt = 0; mt < MT; mt++)
#pragma unroll
                for (int nt = 0; nt < NTT; nt++)
                    mma_16816<DT>(acc[mt][nt], a[mt], b[nt]);
        }
    };

    const int NIT = Kp / BK;
    load_stage(0, 0);  cp_commit();
    load_stage(1, BK); cp_commit();

#pragma unroll 1
    for (int it = 0; it < NIT; ++it) {
        if (it + 1 < NIT) cp_wait1(); else cp_wait0();
        __syncthreads();
        compute_stage(it % 3);
        if (it + 2 < NIT) { load_stage((it + 2) % 3, (it + 2) * BK); cp_commit(); }
    }

    // ---------------- epilogue ----------------
    const int grp = lane >> 2;
    const int tig = lane & 3;
#pragma unroll
    for (int mt = 0; mt < MT; mt++) {
        int r = row0 + mB + mt * 16 + grp;
        float e0 = 0.0f, e1 = 0.0f;
#pragma unroll
        for (int nt = 0; nt < NTT; nt++) {
            int c = col0 + nB + nt * 8 + tig * 2;
            if (c < Ncols) {
                float x0 = acc[mt][nt][0], x1 = acc[mt][nt][1];
                float x2 = acc[mt][nt][2], x3 = acc[mt][nt][3];
                if (bias) {
                    float b0 = bias[c], b1 = bias[c + 1];
                    x0 += b0; x1 += b1; x2 += b0; x3 += b1;
                }
                if (EPI == 1) {
                    x0 = fmaxf(x0, 0.f); x1 = fmaxf(x1, 0.f);
                    x2 = fmaxf(x2, 0.f); x3 = fmaxf(x3, 0.f);
                    size_t kp3 = 3 * (size_t)Ncols;
                    store_triple2(P3 + (size_t)r       * kp3 + 3 * c, x0, x1);
                    store_triple2(P3 + (size_t)(r + 8) * kp3 + 3 * c, x2, x3);
                } else {
                    if (EPI == 2) {
                        const float2 ra = *(const float2*)&R[(size_t)r       * Ncols + c];
                        const float2 rb = *(const float2*)&R[(size_t)(r + 8) * Ncols + c];
                        x0 += ra.x; x1 += ra.y; x2 += rb.x; x3 += rb.y;
                    }
                    if (EPI == 4) {
                        e0 += __expf(x0 - LM0) + __expf(x1 - LM0);
                        e1 += __expf(x2 - LM0) + __expf(x3 - LM0);
                    }
                    *(float2*)&C[(size_t)r       * Ncols + c] = make_float2(x0, x1);
                    *(float2*)&C[(size_t)(r + 8) * Ncols + c] = make_float2(x2, x3);
                }
            }
        }
        if constexpr (EPI == 4) {
            e0 += __shfl_xor_sync(0xffffffff, e0, 1);
            e0 += __shfl_xor_sync(0xffffffff, e0, 2);
            e1 += __shfl_xor_sync(0xffffffff, e1, 1);
            e1 += __shfl_xor_sync(0xffffffff, e1, 2);
            if (tig == 0) {
                sm_es[wc][mB + mt * 16 + grp]     = e0;
                sm_es[wc][mB + mt * 16 + grp + 8] = e1;
            }
        }
    }
    if constexpr (EPI == 4) {
        __syncthreads();
        if (tid < BM) {
            float es = sm_es[0][tid] + sm_es[1][tid] + sm_es[2][tid] + sm_es[3][tid];
            epart[(size_t)(row0 + tid) * gridDim.y + blockIdx.y] = es;
        }
    }
}

// ---------------- key-parallel tiled causal attention (round-11 proven) ------
// 512 threads (16 warps), warp = one query row; lane = one key per 32-key batch.
#define QR 16
__global__ void __launch_bounds__(512, 1)
attn_kernel(const float* __restrict__ q,
            const float* __restrict__ k,
            const float* __restrict__ v,
            __nv_bfloat16* __restrict__ op)
{
    __shared__ __align__(16) float kt[64 * 65];   // [d][key], pad 65
    __shared__ __align__(16) float vs[64 * 64];   // [key][d]

    const int tid  = threadIdx.x;
    const int wid  = tid >> 5;
    const int lane = tid & 31;
    const int qt0  = blockIdx.x * QR;
    const int h    = blockIdx.y;
    const int b    = blockIdx.z;
    const int t    = qt0 + wid;

    float qreg[64];
    size_t qb = ((size_t)(b * NT + t) * NH + h) * DH;
#pragma unroll
    for (int d = 0; d < 64; d += 4) {
        float4 qv = *(const float4*)&q[qb + d];
        qreg[d] = qv.x; qreg[d + 1] = qv.y; qreg[d + 2] = qv.z; qreg[d + 3] = qv.w;
    }

    float m = -INFINITY, l = 0.0f, o0 = 0.0f, o1 = 0.0f;
    const float scale = 0.125f;
    const int lr = tid >> 3;
    const int lc = (tid & 7) * 8;

    for (int s0 = 0; s0 <= qt0 + QR - 1; s0 += 64) {
        __syncthreads();
        {
            size_t gb = ((size_t)(b * NT + s0 + lr) * NH + h) * DH + lc;
            float4 k0 = *(const float4*)&k[gb];
            float4 k1 = *(const float4*)&k[gb + 4];
            kt[(lc + 0) * 65 + lr] = k0.x; kt[(lc + 1) * 65 + lr] = k0.y;
            kt[(lc + 2) * 65 + lr] = k0.z; kt[(lc + 3) * 65 + lr] = k0.w;
            kt[(lc + 4) * 65 + lr] = k1.x; kt[(lc + 5) * 65 + lr] = k1.y;
            kt[(lc + 6) * 65 + lr] = k1.z; kt[(lc + 7) * 65 + lr] = k1.w;
            *(float4*)&vs[lr * 64 + lc]     = *(const float4*)&v[gb];
            *(float4*)&vs[lr * 64 + lc + 4] = *(const float4*)&v[gb + 4];
        }
        __syncthreads();

        int nvalid = t - s0 + 1;
        if (nvalid > 64) nvalid = 64;
#pragma unroll 1
        for (int sb = 0; sb < nvalid; sb += 32) {
            int key = sb + lane;
            float sc = -INFINITY;
            if (key < nvalid) {
                float a = 0.0f;
#pragma unroll
                for (int d = 0; d < 64; d++)
                    a = fmaf(qreg[d], kt[d * 65 + key], a);
                sc = a * scale;
            }
            float mb = sc;
#pragma unroll
            for (int off = 16; off > 0; off >>= 1)
                mb = fmaxf(mb, __shfl_xor_sync(0xffffffff, mb, off));
            float mn = fmaxf(m, mb);
            float c  = __expf(m - mn);
            float p  = __expf(sc - mn);
            float ps = p;
#pragma unroll
            for (int off = 16; off > 0; off >>= 1)
                ps += __shfl_xor_sync(0xffffffff, ps, off);
            o0 *= c; o1 *= c;
            l = l * c + ps;
            m = mn;
#pragma unroll
            for (int i = 0; i < 32; i++) {
                float pi = __shfl_sync(0xffffffff, p, i);
                float2 vv = *(const float2*)&vs[(sb + i) * 64 + 2 * lane];
                o0 = fmaf(pi, vv.x, o0);
                o1 = fmaf(pi, vv.y, o1);
            }
        }
    }
    float inv = 1.0f / l;
    size_t tb = (size_t)(b * NT + t) * KP1 + 3 * (h * DH + 2 * lane);
    store_triple2(op + tb, o0 * inv, o1 * inv);
}

// ---------------- loss: gather partial exp-sums + target logit --------------
__global__ void loss_final_kernel(const float* __restrict__ partial,
                                  const float* __restrict__ logits,
                                  const int* __restrict__ tgt,
                                  float* __restrict__ rowloss)
{
    int r    = blockIdx.x * 8 + (threadIdx.x >> 5);
    int lane = threadIdx.x & 31;
    const float* pr = partial + (size_t)r * NCB;
    float s = 0.0f;
    for (int j = lane; j < NCB; j += 32) s += pr[j];
#pragma unroll
    for (int off = 16; off > 0; off >>= 1)
        s += __shfl_xor_sync(0xffffffff, s, off);
    if (lane == 0)
        rowloss[r] = LM0 + logf(s) - logits[(size_t)r * NV + tgt[r]];
}

__global__ void loss_reduce_kernel(const float* __restrict__ rowloss,
                                   float* __restrict__ out)
{
    __shared__ float sh[256];
    int tid = threadIdx.x;
    float s = 0.0f;
    for (int i = tid; i < MROWS; i += 256) s += rowloss[i];
    sh[tid] = s; __syncthreads();
    for (int o = 128; o > 0; o >>= 1) {
        if (tid < o) sh[tid] += sh[tid + o];
        __syncthreads();
    }
    if (tid == 0) out[0] = sh[0] * (1.0f / MROWS);
}

// ---------------- host driver ----------------
extern "C" void kernel_launch(void* const* d_in, const int* in_sizes, int n_in,
                              void* d_out, int out_size)
{
    const int*   idx     = (const int*)  d_in[0];
    const int*   targets = (const int*)  d_in[1];
    const float* emb     = (const float*)d_in[2];
    const float* wq      = (const float*)d_in[3];
    const float* wk      = (const float*)d_in[4];
    const float* wv      = (const float*)d_in[5];
    const float* wo      = (const float*)d_in[6];
    const float* bo      = (const float*)d_in[7];
    const float* ln1_s   = (const float*)d_in[8];
    const float* ln1_b   = (const float*)d_in[9];
    const float* ln2_s   = (const float*)d_in[10];
    const float* ln2_b   = (const float*)d_in[11];
    const float* w1      = (const float*)d_in[12];
    const float* b1      = (const float*)d_in[13];
    const float* w2      = (const float*)d_in[14];
    const float* b2      = (const float*)d_in[15];
    const float* lnf_s   = (const float*)d_in[16];
    const float* lnf_b   = (const float*)d_in[17];
    const float* w_out   = (const float*)d_in[18];
    const float* b_out   = (const float*)d_in[19];
    float* out = (float*)d_out;

    float *x, *q, *k, *v, *rl, *pt;
    __nv_bfloat16 *hp, *atp, *ffp, *wqp, *wkp, *wvp, *wop, *w1p, *w2p;
    __half *hf, *wouth;
    cudaGetSymbolAddress((void**)&x,     g_x);
    cudaGetSymbolAddress((void**)&q,     g_q);
    cudaGetSymbolAddress((void**)&k,     g_k);
    cudaGetSymbolAddress((void**)&v,     g_v);
    cudaGetSymbolAddress((void**)&rl,    g_rowloss);
    cudaGetSymbolAddress((void**)&pt,    g_partial);
    cudaGetSymbolAddress((void**)&hp,    g_hp);
    cudaGetSymbolAddress((void**)&atp,   g_atp);
    cudaGetSymbolAddress((void**)&ffp,   g_ffp);
    cudaGetSymbolAddress((void**)&hf,    g_hf);
    cudaGetSymbolAddress((void**)&wqp,   g_wqp);
    cudaGetSymbolAddress((void**)&wkp,   g_wkp);
    cudaGetSymbolAddress((void**)&wvp,   g_wvp);
    cudaGetSymbolAddress((void**)&wop,   g_wop);
    cudaGetSymbolAddress((void**)&w1p,   g_w1p);
    cudaGetSymbolAddress((void**)&w2p,   g_w2p);
    cudaGetSymbolAddress((void**)&wouth, g_wouth);

    const int SM_128 = 3 * (128 + 128) * 72 * 2;   // 110592
    const int SM_96  = 3 * (128 +  96) * 72 * 2;   //  96768
    const int SM_256 = 3 * (128 + 256) * 72 * 2;   // 165888
    cudaFuncSetAttribute(mma_gemm<128,128,4,4,0,0>, cudaFuncAttributeMaxDynamicSharedMemorySize, SM_128);
    cudaFuncSetAttribute(mma_gemm<128,128,4,4,1,0>, cudaFuncAttributeMaxDynamicSharedMemorySize, SM_128);
    cudaFuncSetAttribute(mma_gemm<128,96,4,3,2,0>,  cudaFuncAttributeMaxDynamicSharedMemorySize, SM_96);
    cudaFuncSetAttribute(mma_gemm<128,256,4,8,4,1>, cudaFuncAttributeMaxDynamicSharedMemorySize, SM_256);

    pack_all_kernel<<<82944, dim3(32, 8)>>>(wq, wk, wv, wo, w1, w2,
                                            wqp, wkp, wvp, wop, w1p, w2p);
    packw_fp16_kernel<<<dim3(NV / 32, DM / 32, 1), dim3(32, 8)>>>(w_out, wouth, DM, NV);
    embed_kernel<<<(MROWS * DM + 255) / 256, 256>>>(idx, emb, x);

    for (int l = 0; l < NL; l++) {
        size_t oq = (size_t)l * DM * KP1;
        size_t o1 = (size_t)l * DFF * KP1;
        size_t o2 = (size_t)l * DM * KP2;

        ln_kernel<<<MROWS, 384>>>(x, ln1_s + l * DM, ln1_b + l * DM, hp);

        {   // q,k,v = h @ w{q,k,v}
            GemmArgs3 ga = {};
            ga.B[0] = wqp + oq; ga.B[1] = wkp + oq; ga.B[2] = wvp + oq;
            ga.C[0] = q; ga.C[1] = k; ga.C[2] = v;
            mma_gemm<128,128,4,4,0,0><<<dim3(16, 6, 3), 256, SM_128>>>(
                hp, ga, nullptr, nullptr, nullptr, DM, KP1);
        }

        attn_kernel<<<dim3(NT / QR, NH, NB), 512>>>(q, k, v, atp);

        {   // x = x + att @ wo + bo
            GemmArgs3 ga = {};
            ga.B[0] = wop + oq; ga.C[0] = x; ga.bias[0] = bo + l * DM;
            mma_gemm<128,96,4,3,2,0><<<dim3(16, 8, 1), 256, SM_96>>>(
                atp, ga, x, nullptr, nullptr, DM, KP1);
        }

        ln_kernel<<<MROWS, 384>>>(x, ln2_s + l * DM, ln2_b + l * DM, hp);

        {   // ff = relu(h @ w1 + b1)
            GemmArgs3 ga = {};
            ga.B[0] = w1p + o1; ga.bias[0] = b1 + l * DFF;
            mma_gemm<128,128,4,4,1,0><<<dim3(16, 24, 1), 256, SM_128>>>(
                hp, ga, nullptr, ffp, nullptr, DFF, KP1);
        }

        {   // x = x + ff @ w2 + b2
            GemmArgs3 ga = {};
            ga.B[0] = w2p + o2; ga.C[0] = x; ga.bias[0] = b2 + l * DM;
            mma_gemm<128,96,4,3,2,0><<<dim3(16, 8, 1), 256, SM_96>>>(
                ffp, ga, x, nullptr, nullptr, DM, KP2);
        }
    }

    // h = LNf(x) -> fp16
    ln_fp16_kernel<<<MROWS, 384>>>(x, lnf_s, lnf_b, hf);

    // logits = h @ w_out + b_out, fused per-row exp-sum partials (EPI=4)
    {
        GemmArgs3 ga = {};
        ga.B[0] = (const __nv_bfloat16*)wouth;
        ga.C[0] = out; ga.bias[0] = b_out;
        mma_gemm<128,256,4,8,4,1><<<dim3(16, NCB, 1), 256, SM_256>>>(
            (const __nv_bfloat16*)hf, ga, nullptr, nullptr, pt, NV, DM);
    }

    // loss: gather partials + target logit, then mean
    loss_final_kernel<<<MROWS / 8, 256>>>(pt, out, targets, rl);
    loss_reduce_kernel<<<1, 256>>>(rl, out + (size_t)MROWS * NV);
}